// round 2
// baseline (speedup 1.0000x reference)
#include <cuda_runtime.h>
#include <cstdint>
#include <cstddef>

#define HEADS 24
#define HEAD_DIM 128
#define INNER 3072
#define RANK 1024
#define S_IMG 2048
#define S_TXT 512
#define S_REF 2048
#define SQ (S_TXT + S_IMG)          // 2560
#define SK (S_TXT + S_IMG + S_REF)  // 4608

// ---------------- scratch (device globals; no allocation) ----------------
__device__ float g_q[(size_t)SQ * INNER];   // [2560,3072]
__device__ float g_k[(size_t)SK * INNER];   // [4608,3072]
__device__ float g_v[(size_t)SK * INNER];   // [4608,3072]
__device__ float g_t[(size_t)S_REF * RANK]; // lora intermediate [2048,1024]
__device__ float g_o[(size_t)SQ * INNER];   // attention output [2560,3072]

// ---------------- generic SGEMM + optional bias ----------------
// C[M,N] = A[M,K] @ B[K,N] (+ bias[N]).  M%128==0, N%128==0, K%16==0.
__global__ __launch_bounds__(256) void sgemm_bias_kernel(
    const float* __restrict__ A, const float* __restrict__ B,
    const float* __restrict__ bias, float* __restrict__ C,
    int M, int N, int K)
{
    __shared__ float As[128][16];
    __shared__ float Bs[16][128];

    const int bm = blockIdx.y * 128;
    const int bn = blockIdx.x * 128;
    const int tid = threadIdx.x;
    const int tx = tid & 15;
    const int ty = tid >> 4;

    float acc[8][8];
#pragma unroll
    for (int i = 0; i < 8; i++)
#pragma unroll
        for (int j = 0; j < 8; j++) acc[i][j] = 0.f;

    const int arow = tid >> 2;          // 0..63
    const int acol = (tid & 3) * 4;     // 0,4,8,12
    const int brow = tid >> 5;          // 0..7
    const int bcol = (tid & 31) * 4;    // 0..124

    for (int k0 = 0; k0 < K; k0 += 16) {
        float4 a0 = *(const float4*)(A + (size_t)(bm + arow) * K + k0 + acol);
        float4 a1 = *(const float4*)(A + (size_t)(bm + arow + 64) * K + k0 + acol);
        float4 b0 = *(const float4*)(B + (size_t)(k0 + brow) * N + bn + bcol);
        float4 b1 = *(const float4*)(B + (size_t)(k0 + brow + 8) * N + bn + bcol);
        __syncthreads();
        *(float4*)(&As[arow][acol])      = a0;
        *(float4*)(&As[arow + 64][acol]) = a1;
        *(float4*)(&Bs[brow][bcol])      = b0;
        *(float4*)(&Bs[brow + 8][bcol])  = b1;
        __syncthreads();
#pragma unroll
        for (int kk = 0; kk < 16; kk++) {
            float ra[8], rb[8];
#pragma unroll
            for (int i = 0; i < 8; i++) ra[i] = As[ty + i * 16][kk];
#pragma unroll
            for (int j = 0; j < 8; j++) rb[j] = Bs[kk][tx + j * 16];
#pragma unroll
            for (int i = 0; i < 8; i++)
#pragma unroll
                for (int j = 0; j < 8; j++) acc[i][j] += ra[i] * rb[j];
        }
    }

#pragma unroll
    for (int i = 0; i < 8; i++) {
        const int m = bm + ty + i * 16;
#pragma unroll
        for (int j = 0; j < 8; j++) {
            const int n = bn + tx + j * 16;
            float val = acc[i][j];
            if (bias) val += bias[n];
            C[(size_t)m * N + n] = val;
        }
    }
}

// ---------------- fused per-(token,head) RMSNorm + RoPE ----------------
// buf layout [rows, INNER]; head h occupies cols h*128..h*128+127.
// weight = (row < split) ? w0 : w1 ; pass w0=w1=nullptr for no weight.
__global__ void rmsnorm_rope_kernel(
    float* __restrict__ buf,
    const float* __restrict__ w0, const float* __restrict__ w1, int split,
    const float* __restrict__ cos_t, const float* __restrict__ sin_t,
    float eps)
{
    const int row = blockIdx.x;
    const int h   = blockIdx.y;
    const int d   = threadIdx.x;   // 0..127

    float* x = buf + (size_t)row * INNER + h * HEAD_DIM;
    float v = x[d];
    float ss = v * v;
#pragma unroll
    for (int o = 16; o; o >>= 1) ss += __shfl_xor_sync(0xffffffffu, ss, o);
    __shared__ float red[4];
    if ((d & 31) == 0) red[d >> 5] = ss;
    __syncthreads();
    float tot = red[0] + red[1] + red[2] + red[3];
    float r = rsqrtf(tot * (1.0f / HEAD_DIM) + eps);

    const float* w = (row < split) ? w0 : w1;
    float y = v * r;
    if (w) y *= w[d];

    // RoPE: out[2i] = y[2i]*c - y[2i+1]*s ; out[2i+1] = y[2i+1]*c + y[2i]*s
    float other = __shfl_xor_sync(0xffffffffu, y, 1);
    float c = cos_t[(size_t)row * HEAD_DIM + d];
    float s = sin_t[(size_t)row * HEAD_DIM + d];
    float rot = (d & 1) ? other : -other;
    x[d] = y * c + rot * s;
}

// ---------------- flash attention (fp32, online softmax) ----------------
// Q [SQ, INNER], K/V [SK, INNER] with per-head 128 contiguous cols.
// grid = (SQ/64, HEADS), 256 threads, dynamic smem.
#define QS_N   (64 * 128)
#define KS_LD  129
#define KS_N   (64 * KS_LD)
#define SS_LD  65
#define SS_N   (64 * SS_LD)
#define ATTN_SMEM_FLOATS (QS_N + 2 * KS_N + SS_N + 3 * 64)
#define ATTN_SMEM_BYTES  (ATTN_SMEM_FLOATS * 4)

__global__ __launch_bounds__(256) void attn_kernel(
    const float* __restrict__ Q, const float* __restrict__ K,
    const float* __restrict__ V, float* __restrict__ O)
{
    extern __shared__ float sm[];
    float* Qs   = sm;                 // [64][128]
    float* Ks   = Qs + QS_N;          // [64][129]
    float* Vs   = Ks + KS_N;          // [64][129]
    float* Ss   = Vs + KS_N;          // [64][65]
    float* mrow = Ss + SS_N;          // [64]
    float* lrow = mrow + 64;
    float* arow = lrow + 64;

    const int h   = blockIdx.y;
    const int q0  = blockIdx.x * 64;
    const int tid = threadIdx.x;
    const int tx  = tid & 15;
    const int ty  = tid >> 4;
    const float scale = 0.08838834764831845f; // 1/sqrt(128)

    // load Q tile (scaled); Qs row stride 128 -> float4 stores aligned
    for (int i = tid; i < 64 * 32; i += 256) {
        int m  = i >> 5;
        int d4 = (i & 31) * 4;
        float4 qv = *(const float4*)(Q + (size_t)(q0 + m) * INNER + h * HEAD_DIM + d4);
        qv.x *= scale; qv.y *= scale; qv.z *= scale; qv.w *= scale;
        *(float4*)(Qs + m * 128 + d4) = qv;
    }
    if (tid < 64) { mrow[tid] = -1e30f; lrow[tid] = 0.f; }

    float acc[4][8];
#pragma unroll
    for (int i = 0; i < 4; i++)
#pragma unroll
        for (int j = 0; j < 8; j++) acc[i][j] = 0.f;

    for (int k0 = 0; k0 < SK; k0 += 64) {
        __syncthreads();   // protect Ss/Vs reuse; first iter: publish Qs/stats
        // K/V tiles: row stride 129 (odd) keeps reads conflict-free, but
        // means float4 smem stores would be misaligned -> use scalar stores.
        for (int i = tid; i < 64 * 32; i += 256) {
            int n  = i >> 5;
            int d4 = (i & 31) * 4;
            float4 kv = *(const float4*)(K + (size_t)(k0 + n) * INNER + h * HEAD_DIM + d4);
            float4 vv = *(const float4*)(V + (size_t)(k0 + n) * INNER + h * HEAD_DIM + d4);
            float* kd = Ks + n * KS_LD + d4;
            kd[0] = kv.x; kd[1] = kv.y; kd[2] = kv.z; kd[3] = kv.w;
            float* vd = Vs + n * KS_LD + d4;
            vd[0] = vv.x; vd[1] = vv.y; vd[2] = vv.z; vd[3] = vv.w;
        }
        __syncthreads();

        // S = Qs @ Ks^T  (64x64, K=128)
        float s[4][4];
#pragma unroll
        for (int i = 0; i < 4; i++)
#pragma unroll
            for (int j = 0; j < 4; j++) s[i][j] = 0.f;
#pragma unroll 8
        for (int kk = 0; kk < 128; kk++) {
            float ra[4], rb[4];
#pragma unroll
            for (int i = 0; i < 4; i++) ra[i] = Qs[(ty + i * 16) * 128 + kk];
#pragma unroll
            for (int j = 0; j < 4; j++) rb[j] = Ks[(tx + j * 16) * KS_LD + kk];
#pragma unroll
            for (int i = 0; i < 4; i++)
#pragma unroll
                for (int j = 0; j < 4; j++) s[i][j] += ra[i] * rb[j];
        }
#pragma unroll
        for (int i = 0; i < 4; i++)
#pragma unroll
            for (int j = 0; j < 4; j++)
                Ss[(ty + i * 16) * SS_LD + tx + j * 16] = s[i][j];
        __syncthreads();

        // online softmax: 4 lanes per row
        {
            const int r = tid >> 2;
            const int p = tid & 3;
            float mx = -1e30f;
#pragma unroll
            for (int c = 0; c < 16; c++)
                mx = fmaxf(mx, Ss[r * SS_LD + p * 16 + c]);
            mx = fmaxf(mx, __shfl_xor_sync(0xffffffffu, mx, 1));
            mx = fmaxf(mx, __shfl_xor_sync(0xffffffffu, mx, 2));
            float mo = mrow[r];
            float mn = fmaxf(mo, mx);
            float sum = 0.f;
#pragma unroll
            for (int c = 0; c < 16; c++) {
                float pv = __expf(Ss[r * SS_LD + p * 16 + c] - mn);
                Ss[r * SS_LD + p * 16 + c] = pv;
                sum += pv;
            }
            sum += __shfl_xor_sync(0xffffffffu, sum, 1);
            sum += __shfl_xor_sync(0xffffffffu, sum, 2);
            if (p == 0) {
                float al = __expf(mo - mn);
                mrow[r] = mn;
                lrow[r] = lrow[r] * al + sum;
                arow[r] = al;
            }
        }
        __syncthreads();

        // O = alpha*O + P @ V  (64x128, K=64)
        float al[4];
#pragma unroll
        for (int i = 0; i < 4; i++) al[i] = arow[ty + i * 16];
#pragma unroll
        for (int i = 0; i < 4; i++)
#pragma unroll
            for (int j = 0; j < 8; j++) acc[i][j] *= al[i];
#pragma unroll 8
        for (int kk = 0; kk < 64; kk++) {
            float rp[4], rv[8];
#pragma unroll
            for (int i = 0; i < 4; i++) rp[i] = Ss[(ty + i * 16) * SS_LD + kk];
#pragma unroll
            for (int j = 0; j < 8; j++) rv[j] = Vs[kk * KS_LD + tx + j * 16];
#pragma unroll
            for (int i = 0; i < 4; i++)
#pragma unroll
                for (int j = 0; j < 8; j++) acc[i][j] += rp[i] * rv[j];
        }
    }
    __syncthreads();

    float linv[4];
#pragma unroll
    for (int i = 0; i < 4; i++) linv[i] = 1.0f / lrow[ty + i * 16];
#pragma unroll
    for (int i = 0; i < 4; i++)
#pragma unroll
        for (int j = 0; j < 8; j++)
            O[(size_t)(q0 + ty + i * 16) * INNER + h * HEAD_DIM + tx + j * 16] =
                acc[i][j] * linv[i];
}

// ---------------- launch ----------------
extern "C" void kernel_launch(void* const* d_in, const int* in_sizes, int n_in,
                              void* d_out, int out_size)
{
    (void)in_sizes; (void)n_in; (void)out_size;
    const float* hid   = (const float*)d_in[0];
    const float* enc   = (const float*)d_in[1];
    const float* ref   = (const float*)d_in[2];
    const float* rcos  = (const float*)d_in[3];
    const float* rsin  = (const float*)d_in[4];
    const float* ccos  = (const float*)d_in[5];
    const float* csin  = (const float*)d_in[6];
    const float* Wq    = (const float*)d_in[7];
    const float* bq    = (const float*)d_in[8];
    const float* Wk    = (const float*)d_in[9];
    const float* bk    = (const float*)d_in[10];
    const float* Wv    = (const float*)d_in[11];
    const float* bv    = (const float*)d_in[12];
    const float* Waq   = (const float*)d_in[13];
    const float* baq   = (const float*)d_in[14];
    const float* Wak   = (const float*)d_in[15];
    const float* bak   = (const float*)d_in[16];
    const float* Wav   = (const float*)d_in[17];
    const float* bav   = (const float*)d_in[18];
    const float* Wout  = (const float*)d_in[19];
    const float* bout  = (const float*)d_in[20];
    const float* Wadd  = (const float*)d_in[21];
    const float* badd  = (const float*)d_in[22];
    const float* nq_w  = (const float*)d_in[23];
    const float* nk_w  = (const float*)d_in[24];
    const float* naq_w = (const float*)d_in[25];
    const float* nak_w = (const float*)d_in[26];
    const float* lkd   = (const float*)d_in[27];
    const float* lku   = (const float*)d_in[28];
    const float* lvd   = (const float*)d_in[29];
    const float* lvu   = (const float*)d_in[30];

    float *q, *k, *v, *t, *o;
    cudaGetSymbolAddress((void**)&q, g_q);
    cudaGetSymbolAddress((void**)&k, g_k);
    cudaGetSymbolAddress((void**)&v, g_v);
    cudaGetSymbolAddress((void**)&t, g_t);
    cudaGetSymbolAddress((void**)&o, g_o);

    auto gemm = [](const float* A, const float* B, const float* bi, float* C,
                   int M, int N, int K) {
        dim3 grid(N / 128, M / 128);
        sgemm_bias_kernel<<<grid, 256>>>(A, B, bi, C, M, N, K);
    };

    // QKV projections -> concatenated [txt ; img] rows
    gemm(enc, Waq, baq, q,                         S_TXT, INNER, INNER);
    gemm(hid, Wq,  bq,  q + (size_t)S_TXT * INNER, S_IMG, INNER, INNER);
    gemm(enc, Wak, bak, k,                         S_TXT, INNER, INNER);
    gemm(hid, Wk,  bk,  k + (size_t)S_TXT * INNER, S_IMG, INNER, INNER);
    gemm(enc, Wav, bav, v,                         S_TXT, INNER, INNER);
    gemm(hid, Wv,  bv,  v + (size_t)S_TXT * INNER, S_IMG, INNER, INNER);

    // LoRA ref branch -> rows [2560, 4608)
    gemm(ref, lkd, nullptr, t, S_REF, RANK, INNER);
    gemm(t, lku, nullptr, k + (size_t)SQ * INNER, S_REF, INNER, RANK);
    gemm(ref, lvd, nullptr, t, S_REF, RANK, INNER);
    gemm(t, lvu, nullptr, v + (size_t)SQ * INNER, S_REF, INNER, RANK);

    // RMSNorm + RoPE epilogues
    rmsnorm_rope_kernel<<<dim3(SQ, HEADS), 128>>>(q, naq_w, nq_w, S_TXT, rcos, rsin, 1e-6f);
    rmsnorm_rope_kernel<<<dim3(SQ, HEADS), 128>>>(k, nak_w, nk_w, S_TXT, rcos, rsin, 1e-6f);
    rmsnorm_rope_kernel<<<dim3(S_REF, HEADS), 128>>>(k + (size_t)SQ * INNER,
                                                     nullptr, nullptr, 0, ccos, csin, 1e-5f);

    // attention
    cudaFuncSetAttribute(attn_kernel, cudaFuncAttributeMaxDynamicSharedMemorySize,
                         ATTN_SMEM_BYTES);
    attn_kernel<<<dim3(SQ / 64, HEADS), 256, ATTN_SMEM_BYTES>>>(q, k, v, o);

    // output projections: hid_out first, enc_out second
    float* outp = (float*)d_out;
    gemm(o + (size_t)S_TXT * INNER, Wout, bout, outp, S_IMG, INNER, INNER);
    gemm(o, Wadd, badd, outp + (size_t)S_IMG * INNER, S_TXT, INNER, INNER);
}

// round 3
// speedup vs baseline: 1.4958x; 1.4958x over previous
#include <cuda_runtime.h>
#include <cuda_bf16.h>
#include <cstdint>
#include <cstddef>

#define HEADS 24
#define HEAD_DIM 128
#define INNER 3072
#define RANK 1024
#define S_IMG 2048
#define S_TXT 512
#define S_REF 2048
#define SQ (S_TXT + S_IMG)          // 2560
#define SK (S_TXT + S_IMG + S_REF)  // 4608

// ---------------- scratch (device globals; no allocation) ----------------
__device__ float g_q[(size_t)SQ * INNER];
__device__ float g_k[(size_t)SK * INNER];
__device__ float g_v[(size_t)SK * INNER];
__device__ float g_t[(size_t)S_REF * RANK];
__device__ float g_o[(size_t)SQ * INNER];

// bf16 hi/lo splits
__device__ __nv_bfloat16 g_Wh[(size_t)8 * INNER * INNER];  // Waq,Wq,Wak,Wk,Wav,Wv,Wout,Wadd
__device__ __nv_bfloat16 g_Wl[(size_t)8 * INNER * INNER];
__device__ __nv_bfloat16 g_Uh[(size_t)4 * INNER * RANK];   // lkd,lvd,lku,lvu
__device__ __nv_bfloat16 g_Ul[(size_t)4 * INNER * RANK];
__device__ __nv_bfloat16 g_xh[(size_t)(S_IMG + S_TXT + S_REF) * INNER]; // hid,enc,ref
__device__ __nv_bfloat16 g_xl[(size_t)(S_IMG + S_TXT + S_REF) * INNER];
__device__ __nv_bfloat16 g_th[(size_t)S_REF * RANK];
__device__ __nv_bfloat16 g_tl[(size_t)S_REF * RANK];
__device__ __nv_bfloat16 g_oh[(size_t)SQ * INNER];
__device__ __nv_bfloat16 g_ol[(size_t)SQ * INNER];

// ---------------- fp32 -> bf16 hi/lo split ----------------
// n must be a multiple of 1024; grid = n/1024, 256 threads, 4 elems/thread.
__global__ void split_kernel(const float* __restrict__ x,
                             __nv_bfloat16* __restrict__ h,
                             __nv_bfloat16* __restrict__ l)
{
    size_t i = ((size_t)blockIdx.x * 256 + threadIdx.x) * 4;
    float4 v = *(const float4*)(x + i);
    __nv_bfloat16 h0 = __float2bfloat16(v.x);
    __nv_bfloat16 h1 = __float2bfloat16(v.y);
    __nv_bfloat16 h2 = __float2bfloat16(v.z);
    __nv_bfloat16 h3 = __float2bfloat16(v.w);
    __nv_bfloat16 l0 = __float2bfloat16(v.x - __bfloat162float(h0));
    __nv_bfloat16 l1 = __float2bfloat16(v.y - __bfloat162float(h1));
    __nv_bfloat16 l2 = __float2bfloat16(v.z - __bfloat162float(h2));
    __nv_bfloat16 l3 = __float2bfloat16(v.w - __bfloat162float(h3));
    __nv_bfloat162* hp = (__nv_bfloat162*)(h + i);
    hp[0] = __nv_bfloat162{h0, h1}; hp[1] = __nv_bfloat162{h2, h3};
    __nv_bfloat162* lp = (__nv_bfloat162*)(l + i);
    lp[0] = __nv_bfloat162{l0, l1}; lp[1] = __nv_bfloat162{l2, l3};
}

// ---------------- ptx helpers ----------------
#define LDSM4(R, addr) \
    asm volatile("ldmatrix.sync.aligned.m8n8.x4.shared.b16 {%0,%1,%2,%3},[%4];" \
        : "=r"((R)[0]), "=r"((R)[1]), "=r"((R)[2]), "=r"((R)[3]) : "r"(addr))
#define LDSM4T(R, addr) \
    asm volatile("ldmatrix.sync.aligned.m8n8.x4.trans.shared.b16 {%0,%1,%2,%3},[%4];" \
        : "=r"((R)[0]), "=r"((R)[1]), "=r"((R)[2]), "=r"((R)[3]) : "r"(addr))
#define MMA_BF16(C, A, B) \
    asm volatile("mma.sync.aligned.m16n8k16.row.col.f32.bf16.bf16.f32 " \
        "{%0,%1,%2,%3},{%4,%5,%6,%7},{%8,%9},{%0,%1,%2,%3};" \
        : "+f"((C)[0]), "+f"((C)[1]), "+f"((C)[2]), "+f"((C)[3]) \
        : "r"((A)[0]), "r"((A)[1]), "r"((A)[2]), "r"((A)[3]), "r"((B)[0]), "r"((B)[1]))

// ---------------- bf16x3 split-precision GEMM ----------------
// C[M,N] = (Ah+Al)[M,K] @ (Bh+Bl)[K,N] (+bias), fp32 accum, 3 MMA terms.
// M%128==0, N%128==0, K%32==0. 256 threads, warp tiles 32x64 (4x2 warps).
#define A_LD 40   // bf16 elems; 80B row stride (16B aligned, conflict-free)
#define B_LD 136  // 272B row stride

__global__ __launch_bounds__(256, 1) void gemm_bf16x3_kernel(
    const __nv_bfloat16* __restrict__ Ah, const __nv_bfloat16* __restrict__ Al,
    const __nv_bfloat16* __restrict__ Bh, const __nv_bfloat16* __restrict__ Bl,
    const float* __restrict__ bias, float* __restrict__ C,
    int M, int N, int K)
{
    __shared__ __nv_bfloat16 sAh[128 * A_LD], sAl[128 * A_LD];
    __shared__ __nv_bfloat16 sBh[32 * B_LD],  sBl[32 * B_LD];

    const int tid  = threadIdx.x;
    const int lane = tid & 31;
    const int wid  = tid >> 5;
    const int wm   = wid & 3;   // 0..3 -> 32-row slice
    const int wn   = wid >> 2;  // 0..1 -> 64-col slice
    const int bm   = blockIdx.y * 128;
    const int bn   = blockIdx.x * 128;

    const int ar = tid >> 2;         // 0..63
    const int ac = (tid & 3) * 8;    // 0,8,16,24
    const int br = tid >> 4;         // 0..15
    const int bc = (tid & 15) * 8;   // 0..120

    float c[2][8][4];
#pragma unroll
    for (int mi = 0; mi < 2; mi++)
#pragma unroll
        for (int ni = 0; ni < 8; ni++)
#pragma unroll
            for (int r = 0; r < 4; r++) c[mi][ni][r] = 0.f;

    // smem byte addresses (shared space)
    const unsigned sAh_b = (unsigned)__cvta_generic_to_shared(sAh);
    const unsigned sAl_b = (unsigned)__cvta_generic_to_shared(sAl);
    const unsigned sBh_b = (unsigned)__cvta_generic_to_shared(sBh);
    const unsigned sBl_b = (unsigned)__cvta_generic_to_shared(sBl);

    for (int k0 = 0; k0 < K; k0 += 32) {
        uint4 va0 = *(const uint4*)(Ah + (size_t)(bm + ar) * K + k0 + ac);
        uint4 va1 = *(const uint4*)(Ah + (size_t)(bm + ar + 64) * K + k0 + ac);
        uint4 wa0 = *(const uint4*)(Al + (size_t)(bm + ar) * K + k0 + ac);
        uint4 wa1 = *(const uint4*)(Al + (size_t)(bm + ar + 64) * K + k0 + ac);
        uint4 vb0 = *(const uint4*)(Bh + (size_t)(k0 + br) * N + bn + bc);
        uint4 vb1 = *(const uint4*)(Bh + (size_t)(k0 + br + 16) * N + bn + bc);
        uint4 wb0 = *(const uint4*)(Bl + (size_t)(k0 + br) * N + bn + bc);
        uint4 wb1 = *(const uint4*)(Bl + (size_t)(k0 + br + 16) * N + bn + bc);
        __syncthreads();
        *(uint4*)(sAh + ar * A_LD + ac)        = va0;
        *(uint4*)(sAh + (ar + 64) * A_LD + ac) = va1;
        *(uint4*)(sAl + ar * A_LD + ac)        = wa0;
        *(uint4*)(sAl + (ar + 64) * A_LD + ac) = wa1;
        *(uint4*)(sBh + br * B_LD + bc)        = vb0;
        *(uint4*)(sBh + (br + 16) * B_LD + bc) = vb1;
        *(uint4*)(sBl + br * B_LD + bc)        = wb0;
        *(uint4*)(sBl + (br + 16) * B_LD + bc) = wb1;
        __syncthreads();

#pragma unroll
        for (int kh = 0; kh < 2; kh++) {
            unsigned ah[2][4], al[2][4];
#pragma unroll
            for (int mi = 0; mi < 2; mi++) {
                unsigned off = (unsigned)(((wm * 32 + mi * 16 + (lane & 15)) * A_LD
                                           + kh * 16 + ((lane >> 4) << 3)) * 2);
                LDSM4(ah[mi], sAh_b + off);
                LDSM4(al[mi], sAl_b + off);
            }
#pragma unroll
            for (int p = 0; p < 4; p++) {
                unsigned bh[4], bl[4];
                unsigned off = (unsigned)(((kh * 16 + (lane & 15)) * B_LD
                                           + wn * 64 + p * 16 + ((lane >> 4) << 3)) * 2);
                LDSM4T(bh, sBh_b + off);
                LDSM4T(bl, sBl_b + off);
#pragma unroll
                for (int mi = 0; mi < 2; mi++) {
                    MMA_BF16(c[mi][2 * p],     ah[mi], bh);
                    MMA_BF16(c[mi][2 * p + 1], ah[mi], bh + 2);
                    MMA_BF16(c[mi][2 * p],     ah[mi], bl);
                    MMA_BF16(c[mi][2 * p + 1], ah[mi], bl + 2);
                    MMA_BF16(c[mi][2 * p],     al[mi], bh);
                    MMA_BF16(c[mi][2 * p + 1], al[mi], bh + 2);
                }
            }
        }
    }

    const int row0 = bm + wm * 32 + (lane >> 2);
    const int col0 = bn + wn * 64 + (lane & 3) * 2;
#pragma unroll
    for (int mi = 0; mi < 2; mi++) {
#pragma unroll
        for (int ni = 0; ni < 8; ni++) {
            int r  = row0 + mi * 16;
            int cc = col0 + ni * 8;
            float b0 = bias ? bias[cc] : 0.f;
            float b1 = bias ? bias[cc + 1] : 0.f;
            *(float2*)(C + (size_t)r * N + cc)       = float2{c[mi][ni][0] + b0, c[mi][ni][1] + b1};
            *(float2*)(C + (size_t)(r + 8) * N + cc) = float2{c[mi][ni][2] + b0, c[mi][ni][3] + b1};
        }
    }
}

// ---------------- fused per-(token,head) RMSNorm + RoPE ----------------
__global__ void rmsnorm_rope_kernel(
    float* __restrict__ buf,
    const float* __restrict__ w0, const float* __restrict__ w1, int split,
    const float* __restrict__ cos_t, const float* __restrict__ sin_t,
    float eps)
{
    const int row = blockIdx.x;
    const int h   = blockIdx.y;
    const int d   = threadIdx.x;

    float* x = buf + (size_t)row * INNER + h * HEAD_DIM;
    float v = x[d];
    float ss = v * v;
#pragma unroll
    for (int o = 16; o; o >>= 1) ss += __shfl_xor_sync(0xffffffffu, ss, o);
    __shared__ float red[4];
    if ((d & 31) == 0) red[d >> 5] = ss;
    __syncthreads();
    float tot = red[0] + red[1] + red[2] + red[3];
    float r = rsqrtf(tot * (1.0f / HEAD_DIM) + eps);

    const float* w = (row < split) ? w0 : w1;
    float y = v * r;
    if (w) y *= w[d];

    float other = __shfl_xor_sync(0xffffffffu, y, 1);
    float c = cos_t[(size_t)row * HEAD_DIM + d];
    float s = sin_t[(size_t)row * HEAD_DIM + d];
    float rot = (d & 1) ? other : -other;
    x[d] = y * c + rot * s;
}

// ---------------- flash attention (fp32, online softmax) ----------------
#define QS_N   (64 * 128)
#define KS_LD  129
#define KS_N   (64 * KS_LD)
#define SS_LD  65
#define SS_N   (64 * SS_LD)
#define ATTN_SMEM_FLOATS (QS_N + 2 * KS_N + SS_N + 3 * 64)
#define ATTN_SMEM_BYTES  (ATTN_SMEM_FLOATS * 4)

__global__ __launch_bounds__(256) void attn_kernel(
    const float* __restrict__ Q, const float* __restrict__ K,
    const float* __restrict__ V, float* __restrict__ O)
{
    extern __shared__ float sm[];
    float* Qs   = sm;
    float* Ks   = Qs + QS_N;
    float* Vs   = Ks + KS_N;
    float* Ss   = Vs + KS_N;
    float* mrow = Ss + SS_N;
    float* lrow = mrow + 64;
    float* arow = lrow + 64;

    const int h   = blockIdx.y;
    const int q0  = blockIdx.x * 64;
    const int tid = threadIdx.x;
    const int tx  = tid & 15;
    const int ty  = tid >> 4;
    const float scale = 0.08838834764831845f;

    for (int i = tid; i < 64 * 32; i += 256) {
        int m  = i >> 5;
        int d4 = (i & 31) * 4;
        float4 qv = *(const float4*)(Q + (size_t)(q0 + m) * INNER + h * HEAD_DIM + d4);
        qv.x *= scale; qv.y *= scale; qv.z *= scale; qv.w *= scale;
        *(float4*)(Qs + m * 128 + d4) = qv;
    }
    if (tid < 64) { mrow[tid] = -1e30f; lrow[tid] = 0.f; }

    float acc[4][8];
#pragma unroll
    for (int i = 0; i < 4; i++)
#pragma unroll
        for (int j = 0; j < 8; j++) acc[i][j] = 0.f;

    for (int k0 = 0; k0 < SK; k0 += 64) {
        __syncthreads();
        for (int i = tid; i < 64 * 32; i += 256) {
            int n  = i >> 5;
            int d4 = (i & 31) * 4;
            float4 kv = *(const float4*)(K + (size_t)(k0 + n) * INNER + h * HEAD_DIM + d4);
            float4 vv = *(const float4*)(V + (size_t)(k0 + n) * INNER + h * HEAD_DIM + d4);
            float* kd = Ks + n * KS_LD + d4;
            kd[0] = kv.x; kd[1] = kv.y; kd[2] = kv.z; kd[3] = kv.w;
            float* vd = Vs + n * KS_LD + d4;
            vd[0] = vv.x; vd[1] = vv.y; vd[2] = vv.z; vd[3] = vv.w;
        }
        __syncthreads();

        float s[4][4];
#pragma unroll
        for (int i = 0; i < 4; i++)
#pragma unroll
            for (int j = 0; j < 4; j++) s[i][j] = 0.f;
#pragma unroll 8
        for (int kk = 0; kk < 128; kk++) {
            float ra[4], rb[4];
#pragma unroll
            for (int i = 0; i < 4; i++) ra[i] = Qs[(ty + i * 16) * 128 + kk];
#pragma unroll
            for (int j = 0; j < 4; j++) rb[j] = Ks[(tx + j * 16) * KS_LD + kk];
#pragma unroll
            for (int i = 0; i < 4; i++)
#pragma unroll
                for (int j = 0; j < 4; j++) s[i][j] += ra[i] * rb[j];
        }
#pragma unroll
        for (int i = 0; i < 4; i++)
#pragma unroll
            for (int j = 0; j < 4; j++)
                Ss[(ty + i * 16) * SS_LD + tx + j * 16] = s[i][j];
        __syncthreads();

        {
            const int r = tid >> 2;
            const int p = tid & 3;
            float mx = -1e30f;
#pragma unroll
            for (int col = 0; col < 16; col++)
                mx = fmaxf(mx, Ss[r * SS_LD + p * 16 + col]);
            mx = fmaxf(mx, __shfl_xor_sync(0xffffffffu, mx, 1));
            mx = fmaxf(mx, __shfl_xor_sync(0xffffffffu, mx, 2));
            float mo = mrow[r];
            float mn = fmaxf(mo, mx);
            float sum = 0.f;
#pragma unroll
            for (int col = 0; col < 16; col++) {
                float pv = __expf(Ss[r * SS_LD + p * 16 + col] - mn);
                Ss[r * SS_LD + p * 16 + col] = pv;
                sum += pv;
            }
            sum += __shfl_xor_sync(0xffffffffu, sum, 1);
            sum += __shfl_xor_sync(0xffffffffu, sum, 2);
            if (p == 0) {
                float al = __expf(mo - mn);
                mrow[r] = mn;
                lrow[r] = lrow[r] * al + sum;
                arow[r] = al;
            }
        }
        __syncthreads();

        float al[4];
#pragma unroll
        for (int i = 0; i < 4; i++) al[i] = arow[ty + i * 16];
#pragma unroll
        for (int i = 0; i < 4; i++)
#pragma unroll
            for (int j = 0; j < 8; j++) acc[i][j] *= al[i];
#pragma unroll 8
        for (int kk = 0; kk < 64; kk++) {
            float rp[4], rv[8];
#pragma unroll
            for (int i = 0; i < 4; i++) rp[i] = Ss[(ty + i * 16) * SS_LD + kk];
#pragma unroll
            for (int j = 0; j < 8; j++) rv[j] = Vs[kk * KS_LD + tx + j * 16];
#pragma unroll
            for (int i = 0; i < 4; i++)
#pragma unroll
                for (int j = 0; j < 8; j++) acc[i][j] += rp[i] * rv[j];
        }
    }
    __syncthreads();

    float linv[4];
#pragma unroll
    for (int i = 0; i < 4; i++) linv[i] = 1.0f / lrow[ty + i * 16];
#pragma unroll
    for (int i = 0; i < 4; i++)
#pragma unroll
        for (int j = 0; j < 8; j++)
            O[(size_t)(q0 + ty + i * 16) * INNER + h * HEAD_DIM + tx + j * 16] =
                acc[i][j] * linv[i];
}

// ---------------- launch ----------------
extern "C" void kernel_launch(void* const* d_in, const int* in_sizes, int n_in,
                              void* d_out, int out_size)
{
    (void)in_sizes; (void)n_in; (void)out_size;
    const float* hid   = (const float*)d_in[0];
    const float* enc   = (const float*)d_in[1];
    const float* ref   = (const float*)d_in[2];
    const float* rcos  = (const float*)d_in[3];
    const float* rsin  = (const float*)d_in[4];
    const float* ccos  = (const float*)d_in[5];
    const float* csin  = (const float*)d_in[6];
    const float* Wq    = (const float*)d_in[7];
    const float* bq    = (const float*)d_in[8];
    const float* Wk    = (const float*)d_in[9];
    const float* bk    = (const float*)d_in[10];
    const float* Wv    = (const float*)d_in[11];
    const float* bv    = (const float*)d_in[12];
    const float* Waq   = (const float*)d_in[13];
    const float* baq   = (const float*)d_in[14];
    const float* Wak   = (const float*)d_in[15];
    const float* bak   = (const float*)d_in[16];
    const float* Wav   = (const float*)d_in[17];
    const float* bav   = (const float*)d_in[18];
    const float* Wout  = (const float*)d_in[19];
    const float* bout  = (const float*)d_in[20];
    const float* Wadd  = (const float*)d_in[21];
    const float* badd  = (const float*)d_in[22];
    const float* nq_w  = (const float*)d_in[23];
    const float* nk_w  = (const float*)d_in[24];
    const float* naq_w = (const float*)d_in[25];
    const float* nak_w = (const float*)d_in[26];
    const float* lkd   = (const float*)d_in[27];
    const float* lku   = (const float*)d_in[28];
    const float* lvd   = (const float*)d_in[29];
    const float* lvu   = (const float*)d_in[30];

    float *q, *k, *v, *t, *o;
    cudaGetSymbolAddress((void**)&q, g_q);
    cudaGetSymbolAddress((void**)&k, g_k);
    cudaGetSymbolAddress((void**)&v, g_v);
    cudaGetSymbolAddress((void**)&t, g_t);
    cudaGetSymbolAddress((void**)&o, g_o);

    __nv_bfloat16 *Wh, *Wl, *Uh, *Ul, *xh, *xl, *th, *tl, *oh, *ol;
    cudaGetSymbolAddress((void**)&Wh, g_Wh);
    cudaGetSymbolAddress((void**)&Wl, g_Wl);
    cudaGetSymbolAddress((void**)&Uh, g_Uh);
    cudaGetSymbolAddress((void**)&Ul, g_Ul);
    cudaGetSymbolAddress((void**)&xh, g_xh);
    cudaGetSymbolAddress((void**)&xl, g_xl);
    cudaGetSymbolAddress((void**)&th, g_th);
    cudaGetSymbolAddress((void**)&tl, g_tl);
    cudaGetSymbolAddress((void**)&oh, g_oh);
    cudaGetSymbolAddress((void**)&ol, g_ol);

    auto split = [](const float* src, __nv_bfloat16* h, __nv_bfloat16* l, size_t n) {
        split_kernel<<<(unsigned)(n >> 10), 256>>>(src, h, l);
    };
    auto gemm = [](const __nv_bfloat16* Ah, const __nv_bfloat16* Al,
                   const __nv_bfloat16* Bh, const __nv_bfloat16* Bl,
                   const float* bi, float* C, int M, int N, int K) {
        dim3 grid(N / 128, M / 128);
        gemm_bf16x3_kernel<<<grid, 256>>>(Ah, Al, Bh, Bl, bi, C, M, N, K);
    };

    const size_t WSZ = (size_t)INNER * INNER;      // 9437184
    const size_t USZ = (size_t)INNER * RANK;       // 3145728
    const size_t off_hid = 0;
    const size_t off_enc = (size_t)S_IMG * INNER;
    const size_t off_ref = (size_t)(S_IMG + S_TXT) * INNER;

    // split weights: order Waq,Wq,Wak,Wk,Wav,Wv,Wout,Wadd
    split(Waq,  Wh + 0 * WSZ, Wl + 0 * WSZ, WSZ);
    split(Wq,   Wh + 1 * WSZ, Wl + 1 * WSZ, WSZ);
    split(Wak,  Wh + 2 * WSZ, Wl + 2 * WSZ, WSZ);
    split(Wk,   Wh + 3 * WSZ, Wl + 3 * WSZ, WSZ);
    split(Wav,  Wh + 4 * WSZ, Wl + 4 * WSZ, WSZ);
    split(Wv,   Wh + 5 * WSZ, Wl + 5 * WSZ, WSZ);
    split(Wout, Wh + 6 * WSZ, Wl + 6 * WSZ, WSZ);
    split(Wadd, Wh + 7 * WSZ, Wl + 7 * WSZ, WSZ);
    split(lkd,  Uh + 0 * USZ, Ul + 0 * USZ, USZ);
    split(lvd,  Uh + 1 * USZ, Ul + 1 * USZ, USZ);
    split(lku,  Uh + 2 * USZ, Ul + 2 * USZ, USZ);
    split(lvu,  Uh + 3 * USZ, Ul + 3 * USZ, USZ);

    // split activations
    split(hid, xh + off_hid, xl + off_hid, (size_t)S_IMG * INNER);
    split(enc, xh + off_enc, xl + off_enc, (size_t)S_TXT * INNER);
    split(ref, xh + off_ref, xl + off_ref, (size_t)S_REF * INNER);

    // QKV projections -> concatenated [txt ; img] rows
    gemm(xh + off_enc, xl + off_enc, Wh + 0 * WSZ, Wl + 0 * WSZ, baq, q,                         S_TXT, INNER, INNER);
    gemm(xh + off_hid, xl + off_hid, Wh + 1 * WSZ, Wl + 1 * WSZ, bq,  q + (size_t)S_TXT * INNER, S_IMG, INNER, INNER);
    gemm(xh + off_enc, xl + off_enc, Wh + 2 * WSZ, Wl + 2 * WSZ, bak, k,                         S_TXT, INNER, INNER);
    gemm(xh + off_hid, xl + off_hid, Wh + 3 * WSZ, Wl + 3 * WSZ, bk,  k + (size_t)S_TXT * INNER, S_IMG, INNER, INNER);
    gemm(xh + off_enc, xl + off_enc, Wh + 4 * WSZ, Wl + 4 * WSZ, bav, v,                         S_TXT, INNER, INNER);
    gemm(xh + off_hid, xl + off_hid, Wh + 5 * WSZ, Wl + 5 * WSZ, bv,  v + (size_t)S_TXT * INNER, S_IMG, INNER, INNER);

    // LoRA ref branch -> rows [2560, 4608)
    gemm(xh + off_ref, xl + off_ref, Uh + 0 * USZ, Ul + 0 * USZ, nullptr, t, S_REF, RANK, INNER);
    split(t, th, tl, (size_t)S_REF * RANK);
    gemm(th, tl, Uh + 2 * USZ, Ul + 2 * USZ, nullptr, k + (size_t)SQ * INNER, S_REF, INNER, RANK);
    gemm(xh + off_ref, xl + off_ref, Uh + 1 * USZ, Ul + 1 * USZ, nullptr, t, S_REF, RANK, INNER);
    split(t, th, tl, (size_t)S_REF * RANK);
    gemm(th, tl, Uh + 3 * USZ, Ul + 3 * USZ, nullptr, v + (size_t)SQ * INNER, S_REF, INNER, RANK);

    // RMSNorm + RoPE epilogues
    rmsnorm_rope_kernel<<<dim3(SQ, HEADS), 128>>>(q, naq_w, nq_w, S_TXT, rcos, rsin, 1e-6f);
    rmsnorm_rope_kernel<<<dim3(SQ, HEADS), 128>>>(k, nak_w, nk_w, S_TXT, rcos, rsin, 1e-6f);
    rmsnorm_rope_kernel<<<dim3(S_REF, HEADS), 128>>>(k + (size_t)SQ * INNER,
                                                     nullptr, nullptr, 0, ccos, csin, 1e-5f);

    // attention (fp32)
    cudaFuncSetAttribute(attn_kernel, cudaFuncAttributeMaxDynamicSharedMemorySize,
                         ATTN_SMEM_BYTES);
    attn_kernel<<<dim3(SQ / 64, HEADS), 256, ATTN_SMEM_BYTES>>>(q, k, v, o);

    // output projections (split attn output first)
    split(o, oh, ol, (size_t)SQ * INNER);
    float* outp = (float*)d_out;
    gemm(oh + (size_t)S_TXT * INNER, ol + (size_t)S_TXT * INNER,
         Wh + 6 * WSZ, Wl + 6 * WSZ, bout, outp, S_IMG, INNER, INNER);
    gemm(oh, ol, Wh + 7 * WSZ, Wl + 7 * WSZ, badd,
         outp + (size_t)S_IMG * INNER, S_TXT, INNER, INNER);
}

// round 4
// speedup vs baseline: 2.5963x; 1.7357x over previous
#include <cuda_runtime.h>
#include <cuda_bf16.h>
#include <cstdint>
#include <cstddef>

#define HEADS 24
#define HEAD_DIM 128
#define INNER 3072
#define RANK 1024
#define S_IMG 2048
#define S_TXT 512
#define S_REF 2048
#define SQ (S_TXT + S_IMG)          // 2560
#define SK (S_TXT + S_IMG + S_REF)  // 4608

// ---------------- scratch (device globals; no allocation) ----------------
__device__ float g_q[(size_t)SQ * INNER];   // fp32 GEMM outputs (pre-norm)
__device__ float g_k[(size_t)SK * INNER];
__device__ float g_v[(size_t)SK * INNER];
__device__ float g_t[(size_t)S_REF * RANK];

// bf16 hi/lo splits
__device__ __nv_bfloat16 g_Wh[(size_t)8 * INNER * INNER];
__device__ __nv_bfloat16 g_Wl[(size_t)8 * INNER * INNER];
__device__ __nv_bfloat16 g_Uh[(size_t)4 * INNER * RANK];
__device__ __nv_bfloat16 g_Ul[(size_t)4 * INNER * RANK];
__device__ __nv_bfloat16 g_xh[(size_t)(S_IMG + S_TXT + S_REF) * INNER];
__device__ __nv_bfloat16 g_xl[(size_t)(S_IMG + S_TXT + S_REF) * INNER];
__device__ __nv_bfloat16 g_th[(size_t)S_REF * RANK];
__device__ __nv_bfloat16 g_tl[(size_t)S_REF * RANK];
__device__ __nv_bfloat16 g_oh[(size_t)SQ * INNER];
__device__ __nv_bfloat16 g_ol[(size_t)SQ * INNER];
// attention inputs (post norm/rope), bf16 hi/lo
__device__ __nv_bfloat16 g_qh[(size_t)SQ * INNER];
__device__ __nv_bfloat16 g_ql[(size_t)SQ * INNER];
__device__ __nv_bfloat16 g_kh[(size_t)SK * INNER];
__device__ __nv_bfloat16 g_kl[(size_t)SK * INNER];
__device__ __nv_bfloat16 g_vh[(size_t)SK * INNER];
__device__ __nv_bfloat16 g_vl[(size_t)SK * INNER];

// ---------------- fp32 -> bf16 hi/lo split ----------------
__global__ void split_kernel(const float* __restrict__ x,
                             __nv_bfloat16* __restrict__ h,
                             __nv_bfloat16* __restrict__ l)
{
    size_t i = ((size_t)blockIdx.x * 256 + threadIdx.x) * 4;
    float4 v = *(const float4*)(x + i);
    __nv_bfloat16 h0 = __float2bfloat16(v.x);
    __nv_bfloat16 h1 = __float2bfloat16(v.y);
    __nv_bfloat16 h2 = __float2bfloat16(v.z);
    __nv_bfloat16 h3 = __float2bfloat16(v.w);
    __nv_bfloat16 l0 = __float2bfloat16(v.x - __bfloat162float(h0));
    __nv_bfloat16 l1 = __float2bfloat16(v.y - __bfloat162float(h1));
    __nv_bfloat16 l2 = __float2bfloat16(v.z - __bfloat162float(h2));
    __nv_bfloat16 l3 = __float2bfloat16(v.w - __bfloat162float(h3));
    __nv_bfloat162* hp = (__nv_bfloat162*)(h + i);
    hp[0] = __nv_bfloat162{h0, h1}; hp[1] = __nv_bfloat162{h2, h3};
    __nv_bfloat162* lp = (__nv_bfloat162*)(l + i);
    lp[0] = __nv_bfloat162{l0, l1}; lp[1] = __nv_bfloat162{l2, l3};
}

// ---------------- ptx helpers ----------------
#define LDSM4(R, addr) \
    asm volatile("ldmatrix.sync.aligned.m8n8.x4.shared.b16 {%0,%1,%2,%3},[%4];" \
        : "=r"((R)[0]), "=r"((R)[1]), "=r"((R)[2]), "=r"((R)[3]) : "r"(addr))
#define LDSM4T(R, addr) \
    asm volatile("ldmatrix.sync.aligned.m8n8.x4.trans.shared.b16 {%0,%1,%2,%3},[%4];" \
        : "=r"((R)[0]), "=r"((R)[1]), "=r"((R)[2]), "=r"((R)[3]) : "r"(addr))
#define MMA_BF16(C, A, B) \
    asm volatile("mma.sync.aligned.m16n8k16.row.col.f32.bf16.bf16.f32 " \
        "{%0,%1,%2,%3},{%4,%5,%6,%7},{%8,%9},{%0,%1,%2,%3};" \
        : "+f"((C)[0]), "+f"((C)[1]), "+f"((C)[2]), "+f"((C)[3]) \
        : "r"((A)[0]), "r"((A)[1]), "r"((A)[2]), "r"((A)[3]), "r"((B)[0]), "r"((B)[1]))
#define MMA_B2(C, A, B0, B1) \
    asm volatile("mma.sync.aligned.m16n8k16.row.col.f32.bf16.bf16.f32 " \
        "{%0,%1,%2,%3},{%4,%5,%6,%7},{%8,%9},{%0,%1,%2,%3};" \
        : "+f"((C)[0]), "+f"((C)[1]), "+f"((C)[2]), "+f"((C)[3]) \
        : "r"((A)[0]), "r"((A)[1]), "r"((A)[2]), "r"((A)[3]), "r"(B0), "r"(B1))

// ---------------- bf16x3 split-precision GEMM ----------------
#define A_LD 40
#define B_LD 136

__global__ __launch_bounds__(256, 1) void gemm_bf16x3_kernel(
    const __nv_bfloat16* __restrict__ Ah, const __nv_bfloat16* __restrict__ Al,
    const __nv_bfloat16* __restrict__ Bh, const __nv_bfloat16* __restrict__ Bl,
    const float* __restrict__ bias, float* __restrict__ C,
    int M, int N, int K)
{
    __shared__ __nv_bfloat16 sAh[128 * A_LD], sAl[128 * A_LD];
    __shared__ __nv_bfloat16 sBh[32 * B_LD],  sBl[32 * B_LD];

    const int tid  = threadIdx.x;
    const int lane = tid & 31;
    const int wid  = tid >> 5;
    const int wm   = wid & 3;
    const int wn   = wid >> 2;
    const int bm   = blockIdx.y * 128;
    const int bn   = blockIdx.x * 128;

    const int ar = tid >> 2;
    const int ac = (tid & 3) * 8;
    const int br = tid >> 4;
    const int bc = (tid & 15) * 8;

    float c[2][8][4];
#pragma unroll
    for (int mi = 0; mi < 2; mi++)
#pragma unroll
        for (int ni = 0; ni < 8; ni++)
#pragma unroll
            for (int r = 0; r < 4; r++) c[mi][ni][r] = 0.f;

    const unsigned sAh_b = (unsigned)__cvta_generic_to_shared(sAh);
    const unsigned sAl_b = (unsigned)__cvta_generic_to_shared(sAl);
    const unsigned sBh_b = (unsigned)__cvta_generic_to_shared(sBh);
    const unsigned sBl_b = (unsigned)__cvta_generic_to_shared(sBl);

    for (int k0 = 0; k0 < K; k0 += 32) {
        uint4 va0 = *(const uint4*)(Ah + (size_t)(bm + ar) * K + k0 + ac);
        uint4 va1 = *(const uint4*)(Ah + (size_t)(bm + ar + 64) * K + k0 + ac);
        uint4 wa0 = *(const uint4*)(Al + (size_t)(bm + ar) * K + k0 + ac);
        uint4 wa1 = *(const uint4*)(Al + (size_t)(bm + ar + 64) * K + k0 + ac);
        uint4 vb0 = *(const uint4*)(Bh + (size_t)(k0 + br) * N + bn + bc);
        uint4 vb1 = *(const uint4*)(Bh + (size_t)(k0 + br + 16) * N + bn + bc);
        uint4 wb0 = *(const uint4*)(Bl + (size_t)(k0 + br) * N + bn + bc);
        uint4 wb1 = *(const uint4*)(Bl + (size_t)(k0 + br + 16) * N + bn + bc);
        __syncthreads();
        *(uint4*)(sAh + ar * A_LD + ac)        = va0;
        *(uint4*)(sAh + (ar + 64) * A_LD + ac) = va1;
        *(uint4*)(sAl + ar * A_LD + ac)        = wa0;
        *(uint4*)(sAl + (ar + 64) * A_LD + ac) = wa1;
        *(uint4*)(sBh + br * B_LD + bc)        = vb0;
        *(uint4*)(sBh + (br + 16) * B_LD + bc) = vb1;
        *(uint4*)(sBl + br * B_LD + bc)        = wb0;
        *(uint4*)(sBl + (br + 16) * B_LD + bc) = wb1;
        __syncthreads();

#pragma unroll
        for (int kh = 0; kh < 2; kh++) {
            unsigned ah[2][4], al[2][4];
#pragma unroll
            for (int mi = 0; mi < 2; mi++) {
                unsigned off = (unsigned)(((wm * 32 + mi * 16 + (lane & 15)) * A_LD
                                           + kh * 16 + ((lane >> 4) << 3)) * 2);
                LDSM4(ah[mi], sAh_b + off);
                LDSM4(al[mi], sAl_b + off);
            }
#pragma unroll
            for (int p = 0; p < 4; p++) {
                unsigned bh[4], bl[4];
                unsigned off = (unsigned)(((kh * 16 + (lane & 15)) * B_LD
                                           + wn * 64 + p * 16 + ((lane >> 4) << 3)) * 2);
                LDSM4T(bh, sBh_b + off);
                LDSM4T(bl, sBl_b + off);
#pragma unroll
                for (int mi = 0; mi < 2; mi++) {
                    MMA_BF16(c[mi][2 * p],     ah[mi], bh);
                    MMA_BF16(c[mi][2 * p + 1], ah[mi], bh + 2);
                    MMA_BF16(c[mi][2 * p],     ah[mi], bl);
                    MMA_BF16(c[mi][2 * p + 1], ah[mi], bl + 2);
                    MMA_BF16(c[mi][2 * p],     al[mi], bh);
                    MMA_BF16(c[mi][2 * p + 1], al[mi], bh + 2);
                }
            }
        }
    }

    const int row0 = bm + wm * 32 + (lane >> 2);
    const int col0 = bn + wn * 64 + (lane & 3) * 2;
#pragma unroll
    for (int mi = 0; mi < 2; mi++) {
#pragma unroll
        for (int ni = 0; ni < 8; ni++) {
            int r  = row0 + mi * 16;
            int cc = col0 + ni * 8;
            float b0 = bias ? bias[cc] : 0.f;
            float b1 = bias ? bias[cc + 1] : 0.f;
            *(float2*)(C + (size_t)r * N + cc)       = float2{c[mi][ni][0] + b0, c[mi][ni][1] + b1};
            *(float2*)(C + (size_t)(r + 8) * N + cc) = float2{c[mi][ni][2] + b0, c[mi][ni][3] + b1};
        }
    }
}

// ---------------- fused RMSNorm + RoPE -> bf16 hi/lo split ----------------
__global__ void rmsnorm_rope_split_kernel(
    const float* __restrict__ src,
    __nv_bfloat16* __restrict__ outh, __nv_bfloat16* __restrict__ outl,
    const float* __restrict__ w0, const float* __restrict__ w1, int split,
    const float* __restrict__ cos_t, const float* __restrict__ sin_t,
    float eps)
{
    const int row = blockIdx.x;
    const int h   = blockIdx.y;
    const int d   = threadIdx.x;

    const float* x = src + (size_t)row * INNER + h * HEAD_DIM;
    float v = x[d];
    float ss = v * v;
#pragma unroll
    for (int o = 16; o; o >>= 1) ss += __shfl_xor_sync(0xffffffffu, ss, o);
    __shared__ float red[4];
    if ((d & 31) == 0) red[d >> 5] = ss;
    __syncthreads();
    float tot = red[0] + red[1] + red[2] + red[3];
    float r = rsqrtf(tot * (1.0f / HEAD_DIM) + eps);

    const float* w = (row < split) ? w0 : w1;
    float y = v * r;
    if (w) y *= w[d];

    float other = __shfl_xor_sync(0xffffffffu, y, 1);
    float c = cos_t[(size_t)row * HEAD_DIM + d];
    float s = sin_t[(size_t)row * HEAD_DIM + d];
    float rot = (d & 1) ? other : -other;
    float out = y * c + rot * s;

    __nv_bfloat16 hv = __float2bfloat16(out);
    __nv_bfloat16 lv = __float2bfloat16(out - __bfloat162float(hv));
    size_t idx = (size_t)row * INNER + h * HEAD_DIM + d;
    outh[idx] = hv;
    outl[idx] = lv;
}

// ---------------- tensor-core flash attention (bf16x3, FA2 style) --------
// grid (SQ/128, HEADS), 256 threads = 8 warps; each warp owns 16 q-rows.
#define LDQ 136
#define ATTN_SMEM_BYTES ((128 * LDQ * 2 + 64 * LDQ * 4) * 2)

__global__ __launch_bounds__(256, 1) void attn_bf16_kernel(
    const __nv_bfloat16* __restrict__ Qh, const __nv_bfloat16* __restrict__ Ql,
    const __nv_bfloat16* __restrict__ Kh, const __nv_bfloat16* __restrict__ Kl,
    const __nv_bfloat16* __restrict__ Vh, const __nv_bfloat16* __restrict__ Vl,
    __nv_bfloat16* __restrict__ Oh, __nv_bfloat16* __restrict__ Ol)
{
    extern __shared__ __nv_bfloat16 smb[];
    __nv_bfloat16* sQh = smb;
    __nv_bfloat16* sQl = sQh + 128 * LDQ;
    __nv_bfloat16* sKh = sQl + 128 * LDQ;
    __nv_bfloat16* sKl = sKh + 64 * LDQ;
    __nv_bfloat16* sVh = sKl + 64 * LDQ;
    __nv_bfloat16* sVl = sVh + 64 * LDQ;

    const int h    = blockIdx.y;
    const int q0   = blockIdx.x * 128;
    const int tid  = threadIdx.x;
    const int lane = tid & 31;
    const int w    = tid >> 5;
    const float scale = 0.08838834764831845f;

    const unsigned sQh_b = (unsigned)__cvta_generic_to_shared(sQh);
    const unsigned sQl_b = (unsigned)__cvta_generic_to_shared(sQl);
    const unsigned sKh_b = (unsigned)__cvta_generic_to_shared(sKh);
    const unsigned sKl_b = (unsigned)__cvta_generic_to_shared(sKl);
    const unsigned sVh_b = (unsigned)__cvta_generic_to_shared(sVh);
    const unsigned sVl_b = (unsigned)__cvta_generic_to_shared(sVl);

    // load Q tile (128 rows x 128 dims, hi+lo)
    for (int i = tid; i < 128 * 16; i += 256) {
        int row = i >> 4;
        int c8  = (i & 15) * 8;
        size_t g = (size_t)(q0 + row) * INNER + h * HEAD_DIM + c8;
        *(uint4*)(sQh + row * LDQ + c8) = *(const uint4*)(Qh + g);
        *(uint4*)(sQl + row * LDQ + c8) = *(const uint4*)(Ql + g);
    }

    float o[16][4];
#pragma unroll
    for (int nt = 0; nt < 16; nt++)
#pragma unroll
        for (int r = 0; r < 4; r++) o[nt][r] = 0.f;
    float m_lo = -1e30f, m_hi = -1e30f, l_lo = 0.f, l_hi = 0.f;

    for (int kt = 0; kt < SK / 64; kt++) {
        __syncthreads();
        for (int i = tid; i < 64 * 16; i += 256) {
            int row = i >> 4;
            int c8  = (i & 15) * 8;
            size_t g = (size_t)(kt * 64 + row) * INNER + h * HEAD_DIM + c8;
            *(uint4*)(sKh + row * LDQ + c8) = *(const uint4*)(Kh + g);
            *(uint4*)(sKl + row * LDQ + c8) = *(const uint4*)(Kl + g);
            *(uint4*)(sVh + row * LDQ + c8) = *(const uint4*)(Vh + g);
            *(uint4*)(sVl + row * LDQ + c8) = *(const uint4*)(Vl + g);
        }
        __syncthreads();

        // ---- S = Q K^T (64 cols), bf16x3 ----
        float c[8][4];
#pragma unroll
        for (int n = 0; n < 8; n++)
#pragma unroll
            for (int r = 0; r < 4; r++) c[n][r] = 0.f;

#pragma unroll
        for (int kk = 0; kk < 8; kk++) {
            unsigned ah[4], al[4];
            unsigned qoff = (unsigned)(((w * 16 + (lane & 15)) * LDQ
                                        + kk * 16 + ((lane >> 4) << 3)) * 2);
            LDSM4(ah, sQh_b + qoff);
            LDSM4(al, sQl_b + qoff);
#pragma unroll
            for (int ng = 0; ng < 4; ng++) {
                unsigned bh[4], bl[4];
                unsigned koff = (unsigned)(((ng * 16 + (lane & 15)) * LDQ
                                            + kk * 16 + ((lane >> 4) << 3)) * 2);
                LDSM4(bh, sKh_b + koff);
                LDSM4(bl, sKl_b + koff);
                MMA_B2(c[2 * ng],     ah, bh[0], bh[2]);
                MMA_B2(c[2 * ng],     ah, bl[0], bl[2]);
                MMA_B2(c[2 * ng],     al, bh[0], bh[2]);
                MMA_B2(c[2 * ng + 1], ah, bh[1], bh[3]);
                MMA_B2(c[2 * ng + 1], ah, bl[1], bl[3]);
                MMA_B2(c[2 * ng + 1], al, bh[1], bh[3]);
            }
        }

        // ---- online softmax in registers ----
        float tmx_lo = -1e30f, tmx_hi = -1e30f;
#pragma unroll
        for (int n = 0; n < 8; n++) {
            c[n][0] *= scale; c[n][1] *= scale; c[n][2] *= scale; c[n][3] *= scale;
            tmx_lo = fmaxf(tmx_lo, fmaxf(c[n][0], c[n][1]));
            tmx_hi = fmaxf(tmx_hi, fmaxf(c[n][2], c[n][3]));
        }
        tmx_lo = fmaxf(tmx_lo, __shfl_xor_sync(0xffffffffu, tmx_lo, 1));
        tmx_lo = fmaxf(tmx_lo, __shfl_xor_sync(0xffffffffu, tmx_lo, 2));
        tmx_hi = fmaxf(tmx_hi, __shfl_xor_sync(0xffffffffu, tmx_hi, 1));
        tmx_hi = fmaxf(tmx_hi, __shfl_xor_sync(0xffffffffu, tmx_hi, 2));

        float mn_lo = fmaxf(m_lo, tmx_lo);
        float mn_hi = fmaxf(m_hi, tmx_hi);
        float al_lo = __expf(m_lo - mn_lo);
        float al_hi = __expf(m_hi - mn_hi);
        m_lo = mn_lo; m_hi = mn_hi;

        unsigned ph[8][2], pl[8][2];
        float sum_lo = 0.f, sum_hi = 0.f;
#pragma unroll
        for (int n = 0; n < 8; n++) {
            float p0 = __expf(c[n][0] - m_lo);
            float p1 = __expf(c[n][1] - m_lo);
            float p2 = __expf(c[n][2] - m_hi);
            float p3 = __expf(c[n][3] - m_hi);
            sum_lo += p0 + p1;
            sum_hi += p2 + p3;
            __nv_bfloat162 h01 = __floats2bfloat162_rn(p0, p1);
            __nv_bfloat162 h23 = __floats2bfloat162_rn(p2, p3);
            __nv_bfloat162 l01 = __floats2bfloat162_rn(p0 - __bfloat162float(h01.x),
                                                       p1 - __bfloat162float(h01.y));
            __nv_bfloat162 l23 = __floats2bfloat162_rn(p2 - __bfloat162float(h23.x),
                                                       p3 - __bfloat162float(h23.y));
            ph[n][0] = *(unsigned*)&h01; ph[n][1] = *(unsigned*)&h23;
            pl[n][0] = *(unsigned*)&l01; pl[n][1] = *(unsigned*)&l23;
        }
        sum_lo += __shfl_xor_sync(0xffffffffu, sum_lo, 1);
        sum_lo += __shfl_xor_sync(0xffffffffu, sum_lo, 2);
        sum_hi += __shfl_xor_sync(0xffffffffu, sum_hi, 1);
        sum_hi += __shfl_xor_sync(0xffffffffu, sum_hi, 2);
        l_lo = l_lo * al_lo + sum_lo;
        l_hi = l_hi * al_hi + sum_hi;

#pragma unroll
        for (int nt = 0; nt < 16; nt++) {
            o[nt][0] *= al_lo; o[nt][1] *= al_lo;
            o[nt][2] *= al_hi; o[nt][3] *= al_hi;
        }

        // ---- O += P V, bf16x3 ----
#pragma unroll
        for (int j = 0; j < 4; j++) {
            unsigned Ah_[4] = {ph[2 * j][0], ph[2 * j][1], ph[2 * j + 1][0], ph[2 * j + 1][1]};
            unsigned Al_[4] = {pl[2 * j][0], pl[2 * j][1], pl[2 * j + 1][0], pl[2 * j + 1][1]};
#pragma unroll
            for (int dp = 0; dp < 8; dp++) {
                unsigned vh4[4], vl4[4];
                unsigned voff = (unsigned)(((j * 16 + (lane & 15)) * LDQ
                                            + dp * 16 + ((lane >> 4) << 3)) * 2);
                LDSM4T(vh4, sVh_b + voff);
                LDSM4T(vl4, sVl_b + voff);
                MMA_B2(o[2 * dp],     Ah_, vh4[0], vh4[1]);
                MMA_B2(o[2 * dp],     Ah_, vl4[0], vl4[1]);
                MMA_B2(o[2 * dp],     Al_, vh4[0], vh4[1]);
                MMA_B2(o[2 * dp + 1], Ah_, vh4[2], vh4[3]);
                MMA_B2(o[2 * dp + 1], Ah_, vl4[2], vl4[3]);
                MMA_B2(o[2 * dp + 1], Al_, vh4[2], vh4[3]);
            }
        }
    }

    // ---- epilogue: divide by l, split to bf16 hi/lo, write ----
    float inv_lo = 1.0f / l_lo;
    float inv_hi = 1.0f / l_hi;
    const int row_lo = q0 + w * 16 + (lane >> 2);
    const int row_hi = row_lo + 8;
    const int cbase  = h * HEAD_DIM + (lane & 3) * 2;
#pragma unroll
    for (int nt = 0; nt < 16; nt++) {
        int d = cbase + nt * 8;
        float v0 = o[nt][0] * inv_lo, v1 = o[nt][1] * inv_lo;
        float v2 = o[nt][2] * inv_hi, v3 = o[nt][3] * inv_hi;
        __nv_bfloat162 h01 = __floats2bfloat162_rn(v0, v1);
        __nv_bfloat162 h23 = __floats2bfloat162_rn(v2, v3);
        __nv_bfloat162 l01 = __floats2bfloat162_rn(v0 - __bfloat162float(h01.x),
                                                   v1 - __bfloat162float(h01.y));
        __nv_bfloat162 l23 = __floats2bfloat162_rn(v2 - __bfloat162float(h23.x),
                                                   v3 - __bfloat162float(h23.y));
        *(__nv_bfloat162*)(Oh + (size_t)row_lo * INNER + d) = h01;
        *(__nv_bfloat162*)(Ol + (size_t)row_lo * INNER + d) = l01;
        *(__nv_bfloat162*)(Oh + (size_t)row_hi * INNER + d) = h23;
        *(__nv_bfloat162*)(Ol + (size_t)row_hi * INNER + d) = l23;
    }
}

// ---------------- launch ----------------
extern "C" void kernel_launch(void* const* d_in, const int* in_sizes, int n_in,
                              void* d_out, int out_size)
{
    (void)in_sizes; (void)n_in; (void)out_size;
    const float* hid   = (const float*)d_in[0];
    const float* enc   = (const float*)d_in[1];
    const float* ref   = (const float*)d_in[2];
    const float* rcos  = (const float*)d_in[3];
    const float* rsin  = (const float*)d_in[4];
    const float* ccos  = (const float*)d_in[5];
    const float* csin  = (const float*)d_in[6];
    const float* Wq    = (const float*)d_in[7];
    const float* bq    = (const float*)d_in[8];
    const float* Wk    = (const float*)d_in[9];
    const float* bk    = (const float*)d_in[10];
    const float* Wv    = (const float*)d_in[11];
    const float* bv    = (const float*)d_in[12];
    const float* Waq   = (const float*)d_in[13];
    const float* baq   = (const float*)d_in[14];
    const float* Wak   = (const float*)d_in[15];
    const float* bak   = (const float*)d_in[16];
    const float* Wav   = (const float*)d_in[17];
    const float* bav   = (const float*)d_in[18];
    const float* Wout  = (const float*)d_in[19];
    const float* bout  = (const float*)d_in[20];
    const float* Wadd  = (const float*)d_in[21];
    const float* badd  = (const float*)d_in[22];
    const float* nq_w  = (const float*)d_in[23];
    const float* nk_w  = (const float*)d_in[24];
    const float* naq_w = (const float*)d_in[25];
    const float* nak_w = (const float*)d_in[26];
    const float* lkd   = (const float*)d_in[27];
    const float* lku   = (const float*)d_in[28];
    const float* lvd   = (const float*)d_in[29];
    const float* lvu   = (const float*)d_in[30];

    float *q, *k, *v, *t;
    cudaGetSymbolAddress((void**)&q, g_q);
    cudaGetSymbolAddress((void**)&k, g_k);
    cudaGetSymbolAddress((void**)&v, g_v);
    cudaGetSymbolAddress((void**)&t, g_t);

    __nv_bfloat16 *Wh, *Wl, *Uh, *Ul, *xh, *xl, *th, *tl, *oh, *ol;
    __nv_bfloat16 *qh, *ql, *kh, *kl, *vh, *vl;
    cudaGetSymbolAddress((void**)&Wh, g_Wh);
    cudaGetSymbolAddress((void**)&Wl, g_Wl);
    cudaGetSymbolAddress((void**)&Uh, g_Uh);
    cudaGetSymbolAddress((void**)&Ul, g_Ul);
    cudaGetSymbolAddress((void**)&xh, g_xh);
    cudaGetSymbolAddress((void**)&xl, g_xl);
    cudaGetSymbolAddress((void**)&th, g_th);
    cudaGetSymbolAddress((void**)&tl, g_tl);
    cudaGetSymbolAddress((void**)&oh, g_oh);
    cudaGetSymbolAddress((void**)&ol, g_ol);
    cudaGetSymbolAddress((void**)&qh, g_qh);
    cudaGetSymbolAddress((void**)&ql, g_ql);
    cudaGetSymbolAddress((void**)&kh, g_kh);
    cudaGetSymbolAddress((void**)&kl, g_kl);
    cudaGetSymbolAddress((void**)&vh, g_vh);
    cudaGetSymbolAddress((void**)&vl, g_vl);

    auto split = [](const float* src, __nv_bfloat16* h, __nv_bfloat16* l, size_t n) {
        split_kernel<<<(unsigned)(n >> 10), 256>>>(src, h, l);
    };
    auto gemm = [](const __nv_bfloat16* Ah, const __nv_bfloat16* Al,
                   const __nv_bfloat16* Bh, const __nv_bfloat16* Bl,
                   const float* bi, float* C, int M, int N, int K) {
        dim3 grid(N / 128, M / 128);
        gemm_bf16x3_kernel<<<grid, 256>>>(Ah, Al, Bh, Bl, bi, C, M, N, K);
    };

    const size_t WSZ = (size_t)INNER * INNER;
    const size_t USZ = (size_t)INNER * RANK;
    const size_t off_hid = 0;
    const size_t off_enc = (size_t)S_IMG * INNER;
    const size_t off_ref = (size_t)(S_IMG + S_TXT) * INNER;

    split(Waq,  Wh + 0 * WSZ, Wl + 0 * WSZ, WSZ);
    split(Wq,   Wh + 1 * WSZ, Wl + 1 * WSZ, WSZ);
    split(Wak,  Wh + 2 * WSZ, Wl + 2 * WSZ, WSZ);
    split(Wk,   Wh + 3 * WSZ, Wl + 3 * WSZ, WSZ);
    split(Wav,  Wh + 4 * WSZ, Wl + 4 * WSZ, WSZ);
    split(Wv,   Wh + 5 * WSZ, Wl + 5 * WSZ, WSZ);
    split(Wout, Wh + 6 * WSZ, Wl + 6 * WSZ, WSZ);
    split(Wadd, Wh + 7 * WSZ, Wl + 7 * WSZ, WSZ);
    split(lkd,  Uh + 0 * USZ, Ul + 0 * USZ, USZ);
    split(lvd,  Uh + 1 * USZ, Ul + 1 * USZ, USZ);
    split(lku,  Uh + 2 * USZ, Ul + 2 * USZ, USZ);
    split(lvu,  Uh + 3 * USZ, Ul + 3 * USZ, USZ);

    split(hid, xh + off_hid, xl + off_hid, (size_t)S_IMG * INNER);
    split(enc, xh + off_enc, xl + off_enc, (size_t)S_TXT * INNER);
    split(ref, xh + off_ref, xl + off_ref, (size_t)S_REF * INNER);

    // QKV projections (fp32 out, pre-norm)
    gemm(xh + off_enc, xl + off_enc, Wh + 0 * WSZ, Wl + 0 * WSZ, baq, q,                         S_TXT, INNER, INNER);
    gemm(xh + off_hid, xl + off_hid, Wh + 1 * WSZ, Wl + 1 * WSZ, bq,  q + (size_t)S_TXT * INNER, S_IMG, INNER, INNER);
    gemm(xh + off_enc, xl + off_enc, Wh + 2 * WSZ, Wl + 2 * WSZ, bak, k,                         S_TXT, INNER, INNER);
    gemm(xh + off_hid, xl + off_hid, Wh + 3 * WSZ, Wl + 3 * WSZ, bk,  k + (size_t)S_TXT * INNER, S_IMG, INNER, INNER);
    gemm(xh + off_enc, xl + off_enc, Wh + 4 * WSZ, Wl + 4 * WSZ, bav, v,                         S_TXT, INNER, INNER);
    gemm(xh + off_hid, xl + off_hid, Wh + 5 * WSZ, Wl + 5 * WSZ, bv,  v + (size_t)S_TXT * INNER, S_IMG, INNER, INNER);

    // LoRA ref branch -> k/v rows [2560, 4608)
    gemm(xh + off_ref, xl + off_ref, Uh + 0 * USZ, Ul + 0 * USZ, nullptr, t, S_REF, RANK, INNER);
    split(t, th, tl, (size_t)S_REF * RANK);
    gemm(th, tl, Uh + 2 * USZ, Ul + 2 * USZ, nullptr, k + (size_t)SQ * INNER, S_REF, INNER, RANK);
    gemm(xh + off_ref, xl + off_ref, Uh + 1 * USZ, Ul + 1 * USZ, nullptr, t, S_REF, RANK, INNER);
    split(t, th, tl, (size_t)S_REF * RANK);
    gemm(th, tl, Uh + 3 * USZ, Ul + 3 * USZ, nullptr, v + (size_t)SQ * INNER, S_REF, INNER, RANK);

    // RMSNorm + RoPE -> bf16 hi/lo attention inputs
    rmsnorm_rope_split_kernel<<<dim3(SQ, HEADS), 128>>>(q, qh, ql, naq_w, nq_w, S_TXT, rcos, rsin, 1e-6f);
    rmsnorm_rope_split_kernel<<<dim3(SQ, HEADS), 128>>>(k, kh, kl, nak_w, nk_w, S_TXT, rcos, rsin, 1e-6f);
    rmsnorm_rope_split_kernel<<<dim3(S_REF, HEADS), 128>>>(
        k + (size_t)SQ * INNER, kh + (size_t)SQ * INNER, kl + (size_t)SQ * INNER,
        nullptr, nullptr, 0, ccos, csin, 1e-5f);
    split(v, vh, vl, (size_t)SK * INNER);

    // tensor-core attention -> oh/ol bf16 hi/lo
    cudaFuncSetAttribute(attn_bf16_kernel, cudaFuncAttributeMaxDynamicSharedMemorySize,
                         ATTN_SMEM_BYTES);
    attn_bf16_kernel<<<dim3(SQ / 128, HEADS), 256, ATTN_SMEM_BYTES>>>(
        qh, ql, kh, kl, vh, vl, oh, ol);

    // output projections
    float* outp = (float*)d_out;
    gemm(oh + (size_t)S_TXT * INNER, ol + (size_t)S_TXT * INNER,
         Wh + 6 * WSZ, Wl + 6 * WSZ, bout, outp, S_IMG, INNER, INNER);
    gemm(oh, ol, Wh + 7 * WSZ, Wl + 7 * WSZ, badd,
         outp + (size_t)S_IMG * INNER, S_TXT, INNER, INNER);
}

// round 5
// speedup vs baseline: 3.0652x; 1.1806x over previous
#include <cuda_runtime.h>
#include <cuda_bf16.h>
#include <cstdint>
#include <cstddef>

#define HEADS 24
#define HEAD_DIM 128
#define INNER 3072
#define RANK 1024
#define S_IMG 2048
#define S_TXT 512
#define S_REF 2048
#define SQ (S_TXT + S_IMG)          // 2560
#define SK (S_TXT + S_IMG + S_REF)  // 4608

// ---------------- scratch (device globals; no allocation) ----------------
__device__ float g_q[(size_t)SQ * INNER];
__device__ float g_k[(size_t)SK * INNER];
__device__ float g_v[(size_t)SK * INNER];
__device__ float g_t[(size_t)S_REF * RANK];

__device__ __nv_bfloat16 g_Wh[(size_t)8 * INNER * INNER];
__device__ __nv_bfloat16 g_Wl[(size_t)8 * INNER * INNER];
__device__ __nv_bfloat16 g_Uh[(size_t)4 * INNER * RANK];
__device__ __nv_bfloat16 g_Ul[(size_t)4 * INNER * RANK];
__device__ __nv_bfloat16 g_xh[(size_t)(S_IMG + S_TXT + S_REF) * INNER];
__device__ __nv_bfloat16 g_xl[(size_t)(S_IMG + S_TXT + S_REF) * INNER];
__device__ __nv_bfloat16 g_th[(size_t)S_REF * RANK];
__device__ __nv_bfloat16 g_tl[(size_t)S_REF * RANK];
__device__ __nv_bfloat16 g_oh[(size_t)SQ * INNER];
__device__ __nv_bfloat16 g_ol[(size_t)SQ * INNER];
__device__ __nv_bfloat16 g_qh[(size_t)SQ * INNER];
__device__ __nv_bfloat16 g_ql[(size_t)SQ * INNER];
__device__ __nv_bfloat16 g_kh[(size_t)SK * INNER];
__device__ __nv_bfloat16 g_kl[(size_t)SK * INNER];
__device__ __nv_bfloat16 g_vh[(size_t)SK * INNER];
__device__ __nv_bfloat16 g_vl[(size_t)SK * INNER];

// ---------------- fp32 -> bf16 hi/lo split ----------------
__global__ void split_kernel(const float* __restrict__ x,
                             __nv_bfloat16* __restrict__ h,
                             __nv_bfloat16* __restrict__ l)
{
    size_t i = ((size_t)blockIdx.x * 256 + threadIdx.x) * 4;
    float4 v = *(const float4*)(x + i);
    __nv_bfloat16 h0 = __float2bfloat16(v.x);
    __nv_bfloat16 h1 = __float2bfloat16(v.y);
    __nv_bfloat16 h2 = __float2bfloat16(v.z);
    __nv_bfloat16 h3 = __float2bfloat16(v.w);
    __nv_bfloat16 l0 = __float2bfloat16(v.x - __bfloat162float(h0));
    __nv_bfloat16 l1 = __float2bfloat16(v.y - __bfloat162float(h1));
    __nv_bfloat16 l2 = __float2bfloat16(v.z - __bfloat162float(h2));
    __nv_bfloat16 l3 = __float2bfloat16(v.w - __bfloat162float(h3));
    __nv_bfloat162* hp = (__nv_bfloat162*)(h + i);
    hp[0] = __nv_bfloat162{h0, h1}; hp[1] = __nv_bfloat162{h2, h3};
    __nv_bfloat162* lp = (__nv_bfloat162*)(l + i);
    lp[0] = __nv_bfloat162{l0, l1}; lp[1] = __nv_bfloat162{l2, l3};
}

// ---------------- ptx helpers ----------------
#define LDSM4(R, addr) \
    asm volatile("ldmatrix.sync.aligned.m8n8.x4.shared.b16 {%0,%1,%2,%3},[%4];" \
        : "=r"((R)[0]), "=r"((R)[1]), "=r"((R)[2]), "=r"((R)[3]) : "r"(addr))
#define LDSM4T(R, addr) \
    asm volatile("ldmatrix.sync.aligned.m8n8.x4.trans.shared.b16 {%0,%1,%2,%3},[%4];" \
        : "=r"((R)[0]), "=r"((R)[1]), "=r"((R)[2]), "=r"((R)[3]) : "r"(addr))
#define MMA_BF16(C, A, B) \
    asm volatile("mma.sync.aligned.m16n8k16.row.col.f32.bf16.bf16.f32 " \
        "{%0,%1,%2,%3},{%4,%5,%6,%7},{%8,%9},{%0,%1,%2,%3};" \
        : "+f"((C)[0]), "+f"((C)[1]), "+f"((C)[2]), "+f"((C)[3]) \
        : "r"((A)[0]), "r"((A)[1]), "r"((A)[2]), "r"((A)[3]), "r"((B)[0]), "r"((B)[1]))
#define MMA_B2(C, A, B0, B1) \
    asm volatile("mma.sync.aligned.m16n8k16.row.col.f32.bf16.bf16.f32 " \
        "{%0,%1,%2,%3},{%4,%5,%6,%7},{%8,%9},{%0,%1,%2,%3};" \
        : "+f"((C)[0]), "+f"((C)[1]), "+f"((C)[2]), "+f"((C)[3]) \
        : "r"((A)[0]), "r"((A)[1]), "r"((A)[2]), "r"((A)[3]), "r"(B0), "r"(B1))

__device__ __forceinline__ void cp16(__nv_bfloat16* dst, const __nv_bfloat16* src) {
    unsigned d = (unsigned)__cvta_generic_to_shared(dst);
    asm volatile("cp.async.cg.shared.global [%0],[%1],16;" :: "r"(d), "l"(src));
}
#define CP_COMMIT() asm volatile("cp.async.commit_group;")
#define CP_WAIT0()  asm volatile("cp.async.wait_group 0;")
#define CP_WAIT1()  asm volatile("cp.async.wait_group 1;")

// ---------------- bf16x3 split-precision GEMM (3-stage cp.async) ---------
#define A_LD 40
#define B_LD 136
#define SA_ELEMS (128 * A_LD)
#define SB_ELEMS (32 * B_LD)
#define GSTAGE_ELEMS (2 * SA_ELEMS + 2 * SB_ELEMS)
#define GEMM_SMEM_BYTES (GSTAGE_ELEMS * 3 * 2)

__global__ __launch_bounds__(256, 1) void gemm_bf16x3_kernel(
    const __nv_bfloat16* __restrict__ Ah, const __nv_bfloat16* __restrict__ Al,
    const __nv_bfloat16* __restrict__ Bh, const __nv_bfloat16* __restrict__ Bl,
    const float* __restrict__ bias, float* __restrict__ C,
    int M, int N, int K)
{
    extern __shared__ __nv_bfloat16 dsm[];

    const int tid  = threadIdx.x;
    const int lane = tid & 31;
    const int wid  = tid >> 5;
    const int wm   = wid & 3;
    const int wn   = wid >> 2;
    const int bm   = blockIdx.y * 128;
    const int bn   = blockIdx.x * 128;

    const int ar = tid >> 2;
    const int ac = (tid & 3) * 8;
    const int br = tid >> 4;
    const int bc = (tid & 15) * 8;

    float c[2][8][4];
#pragma unroll
    for (int mi = 0; mi < 2; mi++)
#pragma unroll
        for (int ni = 0; ni < 8; ni++)
#pragma unroll
            for (int r = 0; r < 4; r++) c[mi][ni][r] = 0.f;

    const int iters = K >> 5;

    auto load_stage = [&](int s, int it) {
        int k0 = it << 5;
        __nv_bfloat16* st  = dsm + s * GSTAGE_ELEMS;
        __nv_bfloat16* pAh = st;
        __nv_bfloat16* pAl = st + SA_ELEMS;
        __nv_bfloat16* pBh = st + 2 * SA_ELEMS;
        __nv_bfloat16* pBl = pBh + SB_ELEMS;
        cp16(pAh + ar * A_LD + ac,        Ah + (size_t)(bm + ar) * K + k0 + ac);
        cp16(pAh + (ar + 64) * A_LD + ac, Ah + (size_t)(bm + ar + 64) * K + k0 + ac);
        cp16(pAl + ar * A_LD + ac,        Al + (size_t)(bm + ar) * K + k0 + ac);
        cp16(pAl + (ar + 64) * A_LD + ac, Al + (size_t)(bm + ar + 64) * K + k0 + ac);
        cp16(pBh + br * B_LD + bc,        Bh + (size_t)(k0 + br) * N + bn + bc);
        cp16(pBh + (br + 16) * B_LD + bc, Bh + (size_t)(k0 + br + 16) * N + bn + bc);
        cp16(pBl + br * B_LD + bc,        Bl + (size_t)(k0 + br) * N + bn + bc);
        cp16(pBl + (br + 16) * B_LD + bc, Bl + (size_t)(k0 + br + 16) * N + bn + bc);
    };

    load_stage(0, 0); CP_COMMIT();
    load_stage(1, 1); CP_COMMIT();

    for (int it = 0; it < iters; it++) {
        CP_WAIT1();
        __syncthreads();
        if (it + 2 < iters) { load_stage((it + 2) % 3, it + 2); CP_COMMIT(); }

        const __nv_bfloat16* st = dsm + (it % 3) * GSTAGE_ELEMS;
        const unsigned sAh_b = (unsigned)__cvta_generic_to_shared(st);
        const unsigned sAl_b = sAh_b + SA_ELEMS * 2;
        const unsigned sBh_b = sAh_b + 4 * SA_ELEMS;
        const unsigned sBl_b = sBh_b + SB_ELEMS * 2;

#pragma unroll
        for (int kh = 0; kh < 2; kh++) {
            unsigned ah[2][4], al[2][4];
#pragma unroll
            for (int mi = 0; mi < 2; mi++) {
                unsigned off = (unsigned)(((wm * 32 + mi * 16 + (lane & 15)) * A_LD
                                           + kh * 16 + ((lane >> 4) << 3)) * 2);
                LDSM4(ah[mi], sAh_b + off);
                LDSM4(al[mi], sAl_b + off);
            }
#pragma unroll
            for (int p = 0; p < 4; p++) {
                unsigned bh[4], bl[4];
                unsigned off = (unsigned)(((kh * 16 + (lane & 15)) * B_LD
                                           + wn * 64 + p * 16 + ((lane >> 4) << 3)) * 2);
                LDSM4T(bh, sBh_b + off);
                LDSM4T(bl, sBl_b + off);
#pragma unroll
                for (int mi = 0; mi < 2; mi++) {
                    MMA_BF16(c[mi][2 * p],     ah[mi], bh);
                    MMA_BF16(c[mi][2 * p + 1], ah[mi], bh + 2);
                    MMA_BF16(c[mi][2 * p],     ah[mi], bl);
                    MMA_BF16(c[mi][2 * p + 1], ah[mi], bl + 2);
                    MMA_BF16(c[mi][2 * p],     al[mi], bh);
                    MMA_BF16(c[mi][2 * p + 1], al[mi], bh + 2);
                }
            }
        }
        __syncthreads();
    }

    const int row0 = bm + wm * 32 + (lane >> 2);
    const int col0 = bn + wn * 64 + (lane & 3) * 2;
#pragma unroll
    for (int mi = 0; mi < 2; mi++) {
#pragma unroll
        for (int ni = 0; ni < 8; ni++) {
            int r  = row0 + mi * 16;
            int cc = col0 + ni * 8;
            float b0 = bias ? bias[cc] : 0.f;
            float b1 = bias ? bias[cc + 1] : 0.f;
            *(float2*)(C + (size_t)r * N + cc)       = float2{c[mi][ni][0] + b0, c[mi][ni][1] + b1};
            *(float2*)(C + (size_t)(r + 8) * N + cc) = float2{c[mi][ni][2] + b0, c[mi][ni][3] + b1};
        }
    }
}

// ---------------- fused RMSNorm + RoPE -> bf16 hi/lo split ----------------
__global__ void rmsnorm_rope_split_kernel(
    const float* __restrict__ src,
    __nv_bfloat16* __restrict__ outh, __nv_bfloat16* __restrict__ outl,
    const float* __restrict__ w0, const float* __restrict__ w1, int split,
    const float* __restrict__ cos_t, const float* __restrict__ sin_t,
    float eps)
{
    const int row = blockIdx.x;
    const int h   = blockIdx.y;
    const int d   = threadIdx.x;

    const float* x = src + (size_t)row * INNER + h * HEAD_DIM;
    float v = x[d];
    float ss = v * v;
#pragma unroll
    for (int o = 16; o; o >>= 1) ss += __shfl_xor_sync(0xffffffffu, ss, o);
    __shared__ float red[4];
    if ((d & 31) == 0) red[d >> 5] = ss;
    __syncthreads();
    float tot = red[0] + red[1] + red[2] + red[3];
    float r = rsqrtf(tot * (1.0f / HEAD_DIM) + eps);

    const float* w = (row < split) ? w0 : w1;
    float y = v * r;
    if (w) y *= w[d];

    float other = __shfl_xor_sync(0xffffffffu, y, 1);
    float c = cos_t[(size_t)row * HEAD_DIM + d];
    float s = sin_t[(size_t)row * HEAD_DIM + d];
    float rot = (d & 1) ? other : -other;
    float out = y * c + rot * s;

    __nv_bfloat16 hv = __float2bfloat16(out);
    __nv_bfloat16 lv = __float2bfloat16(out - __bfloat162float(hv));
    size_t idx = (size_t)row * INNER + h * HEAD_DIM + d;
    outh[idx] = hv;
    outl[idx] = lv;
}

// ---------------- tensor-core flash attention (bf16x3, cp.async KV) ------
#define LDQ 136
#define Q_ELEMS (128 * LDQ)
#define KV_ELEMS (64 * LDQ)
#define KVSTAGE_ELEMS (4 * KV_ELEMS)     // Kh,Kl,Vh,Vl
#define ATTN_SMEM_BYTES ((2 * Q_ELEMS + 2 * KVSTAGE_ELEMS) * 2)

__global__ __launch_bounds__(256, 1) void attn_bf16_kernel(
    const __nv_bfloat16* __restrict__ Qh, const __nv_bfloat16* __restrict__ Ql,
    const __nv_bfloat16* __restrict__ Kh, const __nv_bfloat16* __restrict__ Kl,
    const __nv_bfloat16* __restrict__ Vh, const __nv_bfloat16* __restrict__ Vl,
    __nv_bfloat16* __restrict__ Oh, __nv_bfloat16* __restrict__ Ol)
{
    extern __shared__ __nv_bfloat16 smb[];
    __nv_bfloat16* sQh = smb;
    __nv_bfloat16* sQl = sQh + Q_ELEMS;
    __nv_bfloat16* kvBase = sQl + Q_ELEMS;   // 2 stages of [Kh|Kl|Vh|Vl]

    const int h    = blockIdx.y;
    const int q0   = blockIdx.x * 128;
    const int tid  = threadIdx.x;
    const int lane = tid & 31;
    const int w    = tid >> 5;
    const float scale = 0.08838834764831845f;

    const unsigned sQh_b = (unsigned)__cvta_generic_to_shared(sQh);
    const unsigned sQl_b = sQh_b + Q_ELEMS * 2;

    const int krow = tid >> 2;          // 0..63
    const int kcol = (tid & 3) * 32;    // 4 x uint4 segments per row? -> use loop

    auto load_kv = [&](int s, int kt) {
        __nv_bfloat16* st = kvBase + s * KVSTAGE_ELEMS;
        __nv_bfloat16* pKh = st;
        __nv_bfloat16* pKl = st + KV_ELEMS;
        __nv_bfloat16* pVh = st + 2 * KV_ELEMS;
        __nv_bfloat16* pVl = st + 3 * KV_ELEMS;
#pragma unroll
        for (int seg = 0; seg < 4; seg++) {
            int row = krow;
            int cc  = kcol + seg * 8;
            size_t g = (size_t)(kt * 64 + row) * INNER + h * HEAD_DIM + cc;
            cp16(pKh + row * LDQ + cc, Kh + g);
            cp16(pKl + row * LDQ + cc, Kl + g);
            cp16(pVh + row * LDQ + cc, Vh + g);
            cp16(pVl + row * LDQ + cc, Vl + g);
        }
    };

    load_kv(0, 0); CP_COMMIT();

    // load Q tile (regular loads)
    for (int i = tid; i < 128 * 16; i += 256) {
        int row = i >> 4;
        int c8  = (i & 15) * 8;
        size_t g = (size_t)(q0 + row) * INNER + h * HEAD_DIM + c8;
        *(uint4*)(sQh + row * LDQ + c8) = *(const uint4*)(Qh + g);
        *(uint4*)(sQl + row * LDQ + c8) = *(const uint4*)(Ql + g);
    }

    float o[16][4];
#pragma unroll
    for (int nt = 0; nt < 16; nt++)
#pragma unroll
        for (int r = 0; r < 4; r++) o[nt][r] = 0.f;
    float m_lo = -1e30f, m_hi = -1e30f, l_lo = 0.f, l_hi = 0.f;

    const int NT = SK / 64;
    for (int kt = 0; kt < NT; kt++) {
        CP_WAIT0();
        __syncthreads();
        if (kt + 1 < NT) { load_kv((kt + 1) & 1, kt + 1); CP_COMMIT(); }

        const __nv_bfloat16* st = kvBase + (kt & 1) * KVSTAGE_ELEMS;
        const unsigned sKh_b = (unsigned)__cvta_generic_to_shared(st);
        const unsigned sKl_b = sKh_b + KV_ELEMS * 2;
        const unsigned sVh_b = sKh_b + 2 * KV_ELEMS * 2;
        const unsigned sVl_b = sKh_b + 3 * KV_ELEMS * 2;

        // ---- S = Q K^T ----
        float c[8][4];
#pragma unroll
        for (int n = 0; n < 8; n++)
#pragma unroll
            for (int r = 0; r < 4; r++) c[n][r] = 0.f;

#pragma unroll
        for (int kk = 0; kk < 8; kk++) {
            unsigned ah[4], al[4];
            unsigned qoff = (unsigned)(((w * 16 + (lane & 15)) * LDQ
                                        + kk * 16 + ((lane >> 4) << 3)) * 2);
            LDSM4(ah, sQh_b + qoff);
            LDSM4(al, sQl_b + qoff);
#pragma unroll
            for (int ng = 0; ng < 4; ng++) {
                unsigned bh[4], bl[4];
                unsigned koff = (unsigned)(((ng * 16 + (lane & 15)) * LDQ
                                            + kk * 16 + ((lane >> 4) << 3)) * 2);
                LDSM4(bh, sKh_b + koff);
                LDSM4(bl, sKl_b + koff);
                MMA_B2(c[2 * ng],     ah, bh[0], bh[2]);
                MMA_B2(c[2 * ng],     ah, bl[0], bl[2]);
                MMA_B2(c[2 * ng],     al, bh[0], bh[2]);
                MMA_B2(c[2 * ng + 1], ah, bh[1], bh[3]);
                MMA_B2(c[2 * ng + 1], ah, bl[1], bl[3]);
                MMA_B2(c[2 * ng + 1], al, bh[1], bh[3]);
            }
        }

        // ---- online softmax ----
        float tmx_lo = -1e30f, tmx_hi = -1e30f;
#pragma unroll
        for (int n = 0; n < 8; n++) {
            c[n][0] *= scale; c[n][1] *= scale; c[n][2] *= scale; c[n][3] *= scale;
            tmx_lo = fmaxf(tmx_lo, fmaxf(c[n][0], c[n][1]));
            tmx_hi = fmaxf(tmx_hi, fmaxf(c[n][2], c[n][3]));
        }
        tmx_lo = fmaxf(tmx_lo, __shfl_xor_sync(0xffffffffu, tmx_lo, 1));
        tmx_lo = fmaxf(tmx_lo, __shfl_xor_sync(0xffffffffu, tmx_lo, 2));
        tmx_hi = fmaxf(tmx_hi, __shfl_xor_sync(0xffffffffu, tmx_hi, 1));
        tmx_hi = fmaxf(tmx_hi, __shfl_xor_sync(0xffffffffu, tmx_hi, 2));

        float mn_lo = fmaxf(m_lo, tmx_lo);
        float mn_hi = fmaxf(m_hi, tmx_hi);
        float al_lo = __expf(m_lo - mn_lo);
        float al_hi = __expf(m_hi - mn_hi);
        m_lo = mn_lo; m_hi = mn_hi;

        unsigned ph[8][2], pl[8][2];
        float sum_lo = 0.f, sum_hi = 0.f;
#pragma unroll
        for (int n = 0; n < 8; n++) {
            float p0 = __expf(c[n][0] - m_lo);
            float p1 = __expf(c[n][1] - m_lo);
            float p2 = __expf(c[n][2] - m_hi);
            float p3 = __expf(c[n][3] - m_hi);
            sum_lo += p0 + p1;
            sum_hi += p2 + p3;
            __nv_bfloat162 h01 = __floats2bfloat162_rn(p0, p1);
            __nv_bfloat162 h23 = __floats2bfloat162_rn(p2, p3);
            __nv_bfloat162 l01 = __floats2bfloat162_rn(p0 - __bfloat162float(h01.x),
                                                       p1 - __bfloat162float(h01.y));
            __nv_bfloat162 l23 = __floats2bfloat162_rn(p2 - __bfloat162float(h23.x),
                                                       p3 - __bfloat162float(h23.y));
            ph[n][0] = *(unsigned*)&h01; ph[n][1] = *(unsigned*)&h23;
            pl[n][0] = *(unsigned*)&l01; pl[n][1] = *(unsigned*)&l23;
        }
        sum_lo += __shfl_xor_sync(0xffffffffu, sum_lo, 1);
        sum_lo += __shfl_xor_sync(0xffffffffu, sum_lo, 2);
        sum_hi += __shfl_xor_sync(0xffffffffu, sum_hi, 1);
        sum_hi += __shfl_xor_sync(0xffffffffu, sum_hi, 2);
        l_lo = l_lo * al_lo + sum_lo;
        l_hi = l_hi * al_hi + sum_hi;

#pragma unroll
        for (int nt = 0; nt < 16; nt++) {
            o[nt][0] *= al_lo; o[nt][1] *= al_lo;
            o[nt][2] *= al_hi; o[nt][3] *= al_hi;
        }

        // ---- O += P V ----
#pragma unroll
        for (int j = 0; j < 4; j++) {
            unsigned Ah_[4] = {ph[2 * j][0], ph[2 * j][1], ph[2 * j + 1][0], ph[2 * j + 1][1]};
            unsigned Al_[4] = {pl[2 * j][0], pl[2 * j][1], pl[2 * j + 1][0], pl[2 * j + 1][1]};
#pragma unroll
            for (int dp = 0; dp < 8; dp++) {
                unsigned vh4[4], vl4[4];
                unsigned voff = (unsigned)(((j * 16 + (lane & 15)) * LDQ
                                            + dp * 16 + ((lane >> 4) << 3)) * 2);
                LDSM4T(vh4, sVh_b + voff);
                LDSM4T(vl4, sVl_b + voff);
                MMA_B2(o[2 * dp],     Ah_, vh4[0], vh4[1]);
                MMA_B2(o[2 * dp],     Ah_, vl4[0], vl4[1]);
                MMA_B2(o[2 * dp],     Al_, vh4[0], vh4[1]);
                MMA_B2(o[2 * dp + 1], Ah_, vh4[2], vh4[3]);
                MMA_B2(o[2 * dp + 1], Ah_, vl4[2], vl4[3]);
                MMA_B2(o[2 * dp + 1], Al_, vh4[2], vh4[3]);
            }
        }
        __syncthreads();
    }

    float inv_lo = 1.0f / l_lo;
    float inv_hi = 1.0f / l_hi;
    const int row_lo = q0 + w * 16 + (lane >> 2);
    const int row_hi = row_lo + 8;
    const int cbase  = h * HEAD_DIM + (lane & 3) * 2;
#pragma unroll
    for (int nt = 0; nt < 16; nt++) {
        int d = cbase + nt * 8;
        float v0 = o[nt][0] * inv_lo, v1 = o[nt][1] * inv_lo;
        float v2 = o[nt][2] * inv_hi, v3 = o[nt][3] * inv_hi;
        __nv_bfloat162 h01 = __floats2bfloat162_rn(v0, v1);
        __nv_bfloat162 h23 = __floats2bfloat162_rn(v2, v3);
        __nv_bfloat162 l01 = __floats2bfloat162_rn(v0 - __bfloat162float(h01.x),
                                                   v1 - __bfloat162float(h01.y));
        __nv_bfloat162 l23 = __floats2bfloat162_rn(v2 - __bfloat162float(h23.x),
                                                   v3 - __bfloat162float(h23.y));
        *(__nv_bfloat162*)(Oh + (size_t)row_lo * INNER + d) = h01;
        *(__nv_bfloat162*)(Ol + (size_t)row_lo * INNER + d) = l01;
        *(__nv_bfloat162*)(Oh + (size_t)row_hi * INNER + d) = h23;
        *(__nv_bfloat162*)(Ol + (size_t)row_hi * INNER + d) = l23;
    }
}

// ---------------- launch ----------------
extern "C" void kernel_launch(void* const* d_in, const int* in_sizes, int n_in,
                              void* d_out, int out_size)
{
    (void)in_sizes; (void)n_in; (void)out_size;
    const float* hid   = (const float*)d_in[0];
    const float* enc   = (const float*)d_in[1];
    const float* ref   = (const float*)d_in[2];
    const float* rcos  = (const float*)d_in[3];
    const float* rsin  = (const float*)d_in[4];
    const float* ccos  = (const float*)d_in[5];
    const float* csin  = (const float*)d_in[6];
    const float* Wq    = (const float*)d_in[7];
    const float* bq    = (const float*)d_in[8];
    const float* Wk    = (const float*)d_in[9];
    const float* bk    = (const float*)d_in[10];
    const float* Wv    = (const float*)d_in[11];
    const float* bv    = (const float*)d_in[12];
    const float* Waq   = (const float*)d_in[13];
    const float* baq   = (const float*)d_in[14];
    const float* Wak   = (const float*)d_in[15];
    const float* bak   = (const float*)d_in[16];
    const float* Wav   = (const float*)d_in[17];
    const float* bav   = (const float*)d_in[18];
    const float* Wout  = (const float*)d_in[19];
    const float* bout  = (const float*)d_in[20];
    const float* Wadd  = (const float*)d_in[21];
    const float* badd  = (const float*)d_in[22];
    const float* nq_w  = (const float*)d_in[23];
    const float* nk_w  = (const float*)d_in[24];
    const float* naq_w = (const float*)d_in[25];
    const float* nak_w = (const float*)d_in[26];
    const float* lkd   = (const float*)d_in[27];
    const float* lku   = (const float*)d_in[28];
    const float* lvd   = (const float*)d_in[29];
    const float* lvu   = (const float*)d_in[30];

    float *q, *k, *v, *t;
    cudaGetSymbolAddress((void**)&q, g_q);
    cudaGetSymbolAddress((void**)&k, g_k);
    cudaGetSymbolAddress((void**)&v, g_v);
    cudaGetSymbolAddress((void**)&t, g_t);

    __nv_bfloat16 *Wh, *Wl, *Uh, *Ul, *xh, *xl, *th, *tl, *oh, *ol;
    __nv_bfloat16 *qh, *ql, *kh, *kl, *vh, *vl;
    cudaGetSymbolAddress((void**)&Wh, g_Wh);
    cudaGetSymbolAddress((void**)&Wl, g_Wl);
    cudaGetSymbolAddress((void**)&Uh, g_Uh);
    cudaGetSymbolAddress((void**)&Ul, g_Ul);
    cudaGetSymbolAddress((void**)&xh, g_xh);
    cudaGetSymbolAddress((void**)&xl, g_xl);
    cudaGetSymbolAddress((void**)&th, g_th);
    cudaGetSymbolAddress((void**)&tl, g_tl);
    cudaGetSymbolAddress((void**)&oh, g_oh);
    cudaGetSymbolAddress((void**)&ol, g_ol);
    cudaGetSymbolAddress((void**)&qh, g_qh);
    cudaGetSymbolAddress((void**)&ql, g_ql);
    cudaGetSymbolAddress((void**)&kh, g_kh);
    cudaGetSymbolAddress((void**)&kl, g_kl);
    cudaGetSymbolAddress((void**)&vh, g_vh);
    cudaGetSymbolAddress((void**)&vl, g_vl);

    cudaFuncSetAttribute(gemm_bf16x3_kernel, cudaFuncAttributeMaxDynamicSharedMemorySize,
                         GEMM_SMEM_BYTES);
    cudaFuncSetAttribute(attn_bf16_kernel, cudaFuncAttributeMaxDynamicSharedMemorySize,
                         ATTN_SMEM_BYTES);

    auto split = [](const float* src, __nv_bfloat16* h, __nv_bfloat16* l, size_t n) {
        split_kernel<<<(unsigned)(n >> 10), 256>>>(src, h, l);
    };
    auto gemm = [](const __nv_bfloat16* Ah, const __nv_bfloat16* Al,
                   const __nv_bfloat16* Bh, const __nv_bfloat16* Bl,
                   const float* bi, float* C, int M, int N, int K) {
        dim3 grid(N / 128, M / 128);
        gemm_bf16x3_kernel<<<grid, 256, GEMM_SMEM_BYTES>>>(Ah, Al, Bh, Bl, bi, C, M, N, K);
    };

    const size_t WSZ = (size_t)INNER * INNER;
    const size_t USZ = (size_t)INNER * RANK;
    const size_t off_hid = 0;
    const size_t off_enc = (size_t)S_IMG * INNER;
    const size_t off_ref = (size_t)(S_IMG + S_TXT) * INNER;

    split(Waq,  Wh + 0 * WSZ, Wl + 0 * WSZ, WSZ);
    split(Wq,   Wh + 1 * WSZ, Wl + 1 * WSZ, WSZ);
    split(Wak,  Wh + 2 * WSZ, Wl + 2 * WSZ, WSZ);
    split(Wk,   Wh + 3 * WSZ, Wl + 3 * WSZ, WSZ);
    split(Wav,  Wh + 4 * WSZ, Wl + 4 * WSZ, WSZ);
    split(Wv,   Wh + 5 * WSZ, Wl + 5 * WSZ, WSZ);
    split(Wout, Wh + 6 * WSZ, Wl + 6 * WSZ, WSZ);
    split(Wadd, Wh + 7 * WSZ, Wl + 7 * WSZ, WSZ);
    split(lkd,  Uh + 0 * USZ, Ul + 0 * USZ, USZ);
    split(lvd,  Uh + 1 * USZ, Ul + 1 * USZ, USZ);
    split(lku,  Uh + 2 * USZ, Ul + 2 * USZ, USZ);
    split(lvu,  Uh + 3 * USZ, Ul + 3 * USZ, USZ);

    split(hid, xh + off_hid, xl + off_hid, (size_t)S_IMG * INNER);
    split(enc, xh + off_enc, xl + off_enc, (size_t)S_TXT * INNER);
    split(ref, xh + off_ref, xl + off_ref, (size_t)S_REF * INNER);

    gemm(xh + off_enc, xl + off_enc, Wh + 0 * WSZ, Wl + 0 * WSZ, baq, q,                         S_TXT, INNER, INNER);
    gemm(xh + off_hid, xl + off_hid, Wh + 1 * WSZ, Wl + 1 * WSZ, bq,  q + (size_t)S_TXT * INNER, S_IMG, INNER, INNER);
    gemm(xh + off_enc, xl + off_enc, Wh + 2 * WSZ, Wl + 2 * WSZ, bak, k,                         S_TXT, INNER, INNER);
    gemm(xh + off_hid, xl + off_hid, Wh + 3 * WSZ, Wl + 3 * WSZ, bk,  k + (size_t)S_TXT * INNER, S_IMG, INNER, INNER);
    gemm(xh + off_enc, xl + off_enc, Wh + 4 * WSZ, Wl + 4 * WSZ, bav, v,                         S_TXT, INNER, INNER);
    gemm(xh + off_hid, xl + off_hid, Wh + 5 * WSZ, Wl + 5 * WSZ, bv,  v + (size_t)S_TXT * INNER, S_IMG, INNER, INNER);

    gemm(xh + off_ref, xl + off_ref, Uh + 0 * USZ, Ul + 0 * USZ, nullptr, t, S_REF, RANK, INNER);
    split(t, th, tl, (size_t)S_REF * RANK);
    gemm(th, tl, Uh + 2 * USZ, Ul + 2 * USZ, nullptr, k + (size_t)SQ * INNER, S_REF, INNER, RANK);
    gemm(xh + off_ref, xl + off_ref, Uh + 1 * USZ, Ul + 1 * USZ, nullptr, t, S_REF, RANK, INNER);
    split(t, th, tl, (size_t)S_REF * RANK);
    gemm(th, tl, Uh + 3 * USZ, Ul + 3 * USZ, nullptr, v + (size_t)SQ * INNER, S_REF, INNER, RANK);

    rmsnorm_rope_split_kernel<<<dim3(SQ, HEADS), 128>>>(q, qh, ql, naq_w, nq_w, S_TXT, rcos, rsin, 1e-6f);
    rmsnorm_rope_split_kernel<<<dim3(SQ, HEADS), 128>>>(k, kh, kl, nak_w, nk_w, S_TXT, rcos, rsin, 1e-6f);
    rmsnorm_rope_split_kernel<<<dim3(S_REF, HEADS), 128>>>(
        k + (size_t)SQ * INNER, kh + (size_t)SQ * INNER, kl + (size_t)SQ * INNER,
        nullptr, nullptr, 0, ccos, csin, 1e-5f);
    split(v, vh, vl, (size_t)SK * INNER);

    attn_bf16_kernel<<<dim3(SQ / 128, HEADS), 256, ATTN_SMEM_BYTES>>>(
        qh, ql, kh, kl, vh, vl, oh, ol);

    float* outp = (float*)d_out;
    gemm(oh + (size_t)S_TXT * INNER, ol + (size_t)S_TXT * INNER,
         Wh + 6 * WSZ, Wl + 6 * WSZ, bout, outp, S_IMG, INNER, INNER);
    gemm(oh, ol, Wh + 7 * WSZ, Wl + 7 * WSZ, badd,
         outp + (size_t)S_IMG * INNER, S_TXT, INNER, INNER);
}